// round 13
// baseline (speedup 1.0000x reference)
#include <cuda_runtime.h>
#include <cuda_bf16.h>
#include <math.h>
#include <stdint.h>

// Problem constants (shape-fixed per reference)
#define NN   50000
#define DIM  128
#define NH   8
#define HD   16

// -------- scratch in __device__ globals (no runtime allocation allowed) -----
__device__ float g_Q[NN * DIM];
__device__ float g_K[NN * DIM];
__device__ float g_V[NN * DIM];
__device__ float g_Z[NN * NH];
// Pre-swizzled bf16 weight images (hi / lo split), 4 matrices (q,k,v,e)
__device__ __nv_bfloat16 g_W1img[4][DIM * DIM];
__device__ __nv_bfloat16 g_W2img[4][DIM * DIM];

// ---------------------------------------------------------------------------
__device__ __forceinline__ uint32_t smem_u32(const void* p) {
    uint32_t a;
    asm("{ .reg .u64 t; cvta.to.shared.u64 t, %1; cvt.u32.u64 %0, t; }"
        : "=r"(a) : "l"(p));
    return a;
}

// Swizzled byte offset inside a [rows x 128] bf16 tile (256B rows).
__device__ __forceinline__ uint32_t soff(int r, int k) {
    uint32_t u = (uint32_t)(k >> 3);
    uint32_t us = (u & 8u) | ((u ^ (uint32_t)(r & 7)) & 7u);
    return (uint32_t)r * 256u + us * 16u + (uint32_t)(k & 7) * 2u;
}

__device__ __forceinline__ void ldsm_x4(uint32_t* r, uint32_t addr) {
    asm("ldmatrix.sync.aligned.m8n8.x4.shared.b16 {%0,%1,%2,%3}, [%4];"
        : "=r"(r[0]), "=r"(r[1]), "=r"(r[2]), "=r"(r[3]) : "r"(addr) : "memory");
}

__device__ __forceinline__ void mma16816(float* d, const uint32_t* a,
                                         uint32_t b0, uint32_t b1) {
    asm("mma.sync.aligned.m16n8k16.row.col.f32.bf16.bf16.f32 "
        "{%0,%1,%2,%3}, {%4,%5,%6,%7}, {%8,%9}, {%0,%1,%2,%3};"
        : "+f"(d[0]), "+f"(d[1]), "+f"(d[2]), "+f"(d[3])
        : "r"(a[0]), "r"(a[1]), "r"(a[2]), "r"(a[3]), "r"(b0), "r"(b1));
}

__device__ __forceinline__ void red4(float* p, float a, float b, float c, float d) {
    asm volatile("red.global.add.v4.f32 [%0], {%1, %2, %3, %4};"
                 :: "l"(p), "f"(a), "f"(b), "f"(c), "f"(d) : "memory");
}

// Named barriers (count must include every arriving thread)
#define NBAR_SYNC(id, cnt)   asm volatile("bar.sync %0, %1;"   :: "r"(id), "r"(cnt) : "memory")
#define NBAR_ARRIVE(id, cnt) asm volatile("bar.arrive %0, %1;" :: "r"(id), "r"(cnt) : "memory")

// ---------------- weight prep: fp32 W[k,n] -> swizzled bf16 hi/lo images -----
__global__ __launch_bounds__(256)
void prep_w_kernel(const float* __restrict__ W0, const float* __restrict__ W1,
                   const float* __restrict__ W2, const float* __restrict__ W3,
                   __nv_bfloat16* __restrict__ img1, __nv_bfloat16* __restrict__ img2) {
    int gi = blockIdx.x * 256 + threadIdx.x;
    if (gi >= 4 * DIM * DIM) return;
    int m = gi >> 14;
    int i = gi & (DIM * DIM - 1);
    const float* W = (m == 0) ? W0 : (m == 1) ? W1 : (m == 2) ? W2 : W3;
    int k = i >> 7;
    int n = i & 127;
    float a = W[i];
    __nv_bfloat16 h = __float2bfloat16(a);
    float lo = a - __bfloat162float(h);
    uint32_t off = soff(n, k);
    *(__nv_bfloat16*)((char*)(img1 + (size_t)m * DIM * DIM) + off) = h;
    *(__nv_bfloat16*)((char*)(img2 + (size_t)m * DIM * DIM) + off) = __float2bfloat16(lo);
}

// =================== QKV GEMM (proven R7 config, unchanged) =================
// 512 threads, 16 warps in 4(M)x4(N) grid, 32x32 warp tiles, M-tile 128.
// smem: bias 1K | A[2] 128K (each: A1 32K + A2 32K) | W1 32K | W2 32K = 193K
#define QS_BIAS  0
#define QS_ABUF  1024
#define QS_W1    (1024 + 131072)
#define QS_W2    (1024 + 131072 + 32768)
#define QS_TOTAL (1024 + 131072 + 65536)

__global__ __launch_bounds__(512, 1)
void qkv_gemm_kernel(const float* __restrict__ X,
                     const __nv_bfloat16* __restrict__ W1img,
                     const __nv_bfloat16* __restrict__ W2img,
                     const float* __restrict__ bias,
                     float* __restrict__ C, int M, int nT) {
    extern __shared__ char smem[];
    const uint32_t sb = smem_u32(smem);
    const int tid = threadIdx.x;
    const int wid = tid >> 5;
    const int lid = tid & 31;

    {
        const int4* s1 = (const int4*)W1img;
        const int4* s2 = (const int4*)W2img;
        int4* d1 = (int4*)(smem + QS_W1);
        int4* d2 = (int4*)(smem + QS_W2);
        #pragma unroll
        for (int i = tid; i < 2048; i += 512) { d1[i] = s1[i]; d2[i] = s2[i]; }
    }
    if (tid < 128) *(float*)(smem + QS_BIAS + tid * 4) = bias[tid];

    uint32_t preoff[8];
    int      xoff[8];
    #pragma unroll
    for (int w = 0; w < 8; w++) {
        int j  = tid + w * 512;
        int r  = j >> 5;
        int k4 = (j & 31) << 2;
        preoff[w] = soff(r, k4);
        xoff[w]   = r * DIM + k4;
    }
    auto ldg_wave = [&](int t, int w0, float4* vb) {
        const size_t base = (size_t)t * 128 * DIM;
        const int lim = (M - t * 128) * DIM;
        #pragma unroll
        for (int i = 0; i < 4; i++) {
            int w = w0 + i;
            vb[i] = (xoff[w] < lim) ? *(const float4*)(X + base + xoff[w])
                                    : make_float4(0.f, 0.f, 0.f, 0.f);
        }
    };
    auto cvt_wave = [&](char* abuf, int w0, const float4* vb) {
        #pragma unroll
        for (int i = 0; i < 4; i++) {
            int w = w0 + i;
            float4 v = vb[i];
            __nv_bfloat162 hp0 = __floats2bfloat162_rn(v.x, v.y);
            __nv_bfloat162 hp1 = __floats2bfloat162_rn(v.z, v.w);
            __nv_bfloat162 lp0 = __floats2bfloat162_rn(v.x - __bfloat162float(hp0.x),
                                                       v.y - __bfloat162float(hp0.y));
            __nv_bfloat162 lp1 = __floats2bfloat162_rn(v.z - __bfloat162float(hp1.x),
                                                       v.w - __bfloat162float(hp1.y));
            uint2 hq, lq;
            hq.x = *(uint32_t*)&hp0; hq.y = *(uint32_t*)&hp1;
            lq.x = *(uint32_t*)&lp0; lq.y = *(uint32_t*)&lp1;
            *(uint2*)(abuf + preoff[w])         = hq;
            *(uint2*)(abuf + 32768 + preoff[w]) = lq;
        }
    };

    const int wm = (wid >> 2) * 32;
    const int wn = (wid & 3) * 32;
    const int g  = lid >> 3;
    const int lr = (lid & 7) | ((g & 1) << 3);
    const int kq = (g >> 1) << 3;
    const int cr = lid >> 2;
    const int cc = (lid & 3) * 2;
    const float* sBias = (const float*)(smem + QS_BIAS);

    if ((int)blockIdx.x < nT) {
        float4 vb[4];
        ldg_wave(blockIdx.x, 0, vb);
        cvt_wave(smem + QS_ABUF, 0, vb);
        ldg_wave(blockIdx.x, 4, vb);
        cvt_wave(smem + QS_ABUF, 4, vb);
    }
    __syncthreads();

    int pb = 0;
    for (int t = blockIdx.x; t < nT; t += gridDim.x, pb ^= 1) {
        const uint32_t cur = sb + QS_ABUF + (uint32_t)pb * 65536u;
        char* nxt = smem + QS_ABUF + (pb ^ 1) * 65536;
        const int tn = t + gridDim.x;
        const bool hn = tn < nT;

        float acc[2][4][4];
        #pragma unroll
        for (int i = 0; i < 2; i++)
            #pragma unroll
            for (int j = 0; j < 4; j++)
                #pragma unroll
                for (int u = 0; u < 4; u++) acc[i][j][u] = 0.f;

        float4 vb[4];
        if (hn) ldg_wave(tn, 0, vb);

        #pragma unroll
        for (int half = 0; half < 2; half++) {
            #pragma unroll
            for (int ks = half * 4; ks < half * 4 + 4; ks++) {
                const int k0 = ks * 16 + kq;
                uint32_t a1f[2][4], a2f[2][4], b1f[2][4], b2f[2][4];
                #pragma unroll
                for (int mt = 0; mt < 2; mt++) {
                    ldsm_x4(a1f[mt], cur + soff(wm + mt * 16 + lr, k0));
                    ldsm_x4(a2f[mt], cur + 32768u + soff(wm + mt * 16 + lr, k0));
                }
                #pragma unroll
                for (int nt2 = 0; nt2 < 2; nt2++) {
                    ldsm_x4(b1f[nt2], sb + QS_W1 + soff(wn + nt2 * 16 + lr, k0));
                    ldsm_x4(b2f[nt2], sb + QS_W2 + soff(wn + nt2 * 16 + lr, k0));
                }
                #pragma unroll
                for (int mt = 0; mt < 2; mt++) {
                    mma16816(acc[mt][0], a1f[mt], b1f[0][0], b1f[0][2]);
                    mma16816(acc[mt][1], a1f[mt], b1f[0][1], b1f[0][3]);
                    mma16816(acc[mt][2], a1f[mt], b1f[1][0], b1f[1][2]);
                    mma16816(acc[mt][3], a1f[mt], b1f[1][1], b1f[1][3]);
                }
                #pragma unroll
                for (int mt = 0; mt < 2; mt++) {
                    mma16816(acc[mt][0], a2f[mt], b1f[0][0], b1f[0][2]);
                    mma16816(acc[mt][1], a2f[mt], b1f[0][1], b1f[0][3]);
                    mma16816(acc[mt][2], a2f[mt], b1f[1][0], b1f[1][2]);
                    mma16816(acc[mt][3], a2f[mt], b1f[1][1], b1f[1][3]);
                }
                #pragma unroll
                for (int mt = 0; mt < 2; mt++) {
                    mma16816(acc[mt][0], a1f[mt], b2f[0][0], b2f[0][2]);
                    mma16816(acc[mt][1], a1f[mt], b2f[0][1], b2f[0][3]);
                    mma16816(acc[mt][2], a1f[mt], b2f[1][0], b2f[1][2]);
                    mma16816(acc[mt][3], a1f[mt], b2f[1][1], b2f[1][3]);
                }
            }
            if (hn) {
                cvt_wave(nxt, half * 4, vb);
                if (half == 0) ldg_wave(tn, 4, vb);
            }
        }

        const int row0 = t * 128;
        #pragma unroll
        for (int mt = 0; mt < 2; mt++) {
            #pragma unroll
            for (int nt = 0; nt < 4; nt++) {
                int col = wn + nt * 8 + cc;
                float b0 = sBias[col], b1 = sBias[col + 1];
                int r1 = row0 + wm + mt * 16 + cr;
                if (r1 < M) {
                    float2 o; o.x = acc[mt][nt][0] + b0; o.y = acc[mt][nt][1] + b1;
                    *(float2*)(C + (size_t)r1 * DIM + col) = o;
                }
                int r2 = r1 + 8;
                if (r2 < M) {
                    float2 o; o.x = acc[mt][nt][2] + b0; o.y = acc[mt][nt][3] + b1;
                    *(float2*)(C + (size_t)r2 * DIM + col) = o;
                }
            }
        }
        __syncthreads();
    }
}

// ========= fused E-GEMM + edge scatter, warp-specialized (640 thr) ==========
// Warps 0-15: producers (E-GEMM, M-tile 128, single-buffered A).
// Warps 16-19: consumers (edge processing from smem E tile).
// Named barriers: 1 = producers-only sync (512); 4 = "ESM free" (512 sync +
// 128 arrive); 5 = "ESM full" (128 sync + 512 arrive).
// smem: bias 1K | A1 32K | A2 32K | W1 32K | W2 32K | ESM 67.5K  = 199.7K
#define FS_BIAS  0
#define FS_A1    1024
#define FS_A2    (FS_A1 + 32768)
#define FS_W1    (FS_A2 + 32768)
#define FS_W2    (FS_W1 + 32768)
#define FS_ESM   (FS_W2 + 32768)
#define ESM_STRIDE 132
#define FS_TOTAL (FS_ESM + 128 * ESM_STRIDE * 4)
#define FTHREADS 640

__global__ __launch_bounds__(FTHREADS, 1)
void fused_eg_kernel(const float* __restrict__ EA, const float* __restrict__ be,
                     const int* __restrict__ ei, float* __restrict__ out,
                     int nE, int nT) {
    extern __shared__ char smem[];
    const uint32_t sb = smem_u32(smem);
    const int tid = threadIdx.x;
    const int wid = tid >> 5;
    const int lid = tid & 31;
    const bool producer = wid < 16;

    if (producer) {
        // ---- one-time: weights + bias into smem (producers only) ----
        {
            const int4* s1 = (const int4*)g_W1img[3];
            const int4* s2 = (const int4*)g_W2img[3];
            int4* d1 = (int4*)(smem + FS_W1);
            int4* d2 = (int4*)(smem + FS_W2);
            #pragma unroll
            for (int i = tid; i < 2048; i += 512) { d1[i] = s1[i]; d2[i] = s2[i]; }
        }
        if (tid < 128) *(float*)(smem + FS_BIAS + tid * 4) = be[tid];

        uint32_t preoff[8];
        int      xoff[8];
        #pragma unroll
        for (int w = 0; w < 8; w++) {
            int j  = tid + w * 512;
            int r  = j >> 5;
            int k4 = (j & 31) << 2;
            preoff[w] = soff(r, k4);
            xoff[w]   = r * DIM + k4;
        }
        auto ldg8 = [&](int t, float4* vb) {
            const size_t base = (size_t)t * 128 * DIM;
            const int lim = (nE - t * 128) * DIM;
            #pragma unroll
            for (int w = 0; w < 8; w++)
                vb[w] = (xoff[w] < lim) ? *(const float4*)(EA + base + xoff[w])
                                        : make_float4(0.f, 0.f, 0.f, 0.f);
        };
        auto cvt8 = [&](const float4* vb) {
            #pragma unroll
            for (int w = 0; w < 8; w++) {
                float4 v = vb[w];
                __nv_bfloat162 hp0 = __floats2bfloat162_rn(v.x, v.y);
                __nv_bfloat162 hp1 = __floats2bfloat162_rn(v.z, v.w);
                __nv_bfloat162 lp0 = __floats2bfloat162_rn(v.x - __bfloat162float(hp0.x),
                                                           v.y - __bfloat162float(hp0.y));
                __nv_bfloat162 lp1 = __floats2bfloat162_rn(v.z - __bfloat162float(hp1.x),
                                                           v.w - __bfloat162float(hp1.y));
                uint2 hq, lq;
                hq.x = *(uint32_t*)&hp0; hq.y = *(uint32_t*)&hp1;
                lq.x = *(uint32_t*)&lp0; lq.y = *(uint32_t*)&lp1;
                *(uint2*)(smem + FS_A1 + preoff[w]) = hq;
                *(uint2*)(smem + FS_A2 + preoff[w]) = lq;
            }
        };

        const int wm = (wid >> 2) * 32;
        const int wn = (wid & 3) * 32;
        const int g  = lid >> 3;
        const int lr = (lid & 7) | ((g & 1) << 3);
        const int kq = (g >> 1) << 3;
        const int cr = lid >> 2;
        const int cc = (lid & 3) * 2;
        const float* sBias = (const float*)(smem + FS_BIAS);

        // prologue: first A tile
        float4 vb[8];
        if ((int)blockIdx.x < nT) ldg8(blockIdx.x, vb);
        NBAR_SYNC(1, 512);                 // weights/bias visible to producers
        if ((int)blockIdx.x < nT) cvt8(vb);
        NBAR_SYNC(1, 512);                 // A tile ready

        for (int t = blockIdx.x; t < nT; t += gridDim.x) {
            float acc[2][4][4];
            #pragma unroll
            for (int i = 0; i < 2; i++)
                #pragma unroll
                for (int j = 0; j < 4; j++)
                    #pragma unroll
                    for (int u = 0; u < 4; u++) acc[i][j][u] = 0.f;

            #pragma unroll
            for (int ks = 0; ks < 8; ks++) {
                const int k0 = ks * 16 + kq;
                uint32_t a1f[2][4], a2f[2][4], b1f[2][4], b2f[2][4];
                #pragma unroll
                for (int mt = 0; mt < 2; mt++) {
                    ldsm_x4(a1f[mt], sb + FS_A1 + soff(wm + mt * 16 + lr, k0));
                    ldsm_x4(a2f[mt], sb + FS_A2 + soff(wm + mt * 16 + lr, k0));
                }
                #pragma unroll
                for (int nt2 = 0; nt2 < 2; nt2++) {
                    ldsm_x4(b1f[nt2], sb + FS_W1 + soff(wn + nt2 * 16 + lr, k0));
                    ldsm_x4(b2f[nt2], sb + FS_W2 + soff(wn + nt2 * 16 + lr, k0));
                }
                #pragma unroll
                for (int mt = 0; mt < 2; mt++) {
                    mma16816(acc[mt][0], a1f[mt], b1f[0][0], b1f[0][2]);
                    mma16816(acc[mt][1], a1f[mt], b1f[0][1], b1f[0][3]);
                    mma16816(acc[mt][2], a1f[mt], b1f[1][0], b1f[1][2]);
                    mma16816(acc[mt][3], a1f[mt], b1f[1][1], b1f[1][3]);
                }
                #pragma unroll
                for (int mt = 0; mt < 2; mt++) {
                    mma16816(acc[mt][0], a2f[mt], b1f[0][0], b1f[0][2]);
                    mma16816(acc[mt][1], a2f[mt], b1f[0][1], b1f[0][3]);
                    mma16816(acc[mt][2], a2f[mt], b1f[1][0], b1f[1][2]);
                    mma16816(acc[mt][3], a2f[mt], b1f[1][1], b1f[1][3]);
                }
                #pragma unroll
                for (int mt = 0; mt < 2; mt++) {
                    mma16816(acc[mt][0], a1f[mt], b2f[0][0], b2f[0][2]);
                    mma16816(acc[mt][1], a1f[mt], b2f[0][1], b2f[0][3]);
                    mma16816(acc[mt][2], a1f[mt], b2f[1][0], b2f[1][2]);
                    mma16816(acc[mt][3], a1f[mt], b2f[1][1], b2f[1][3]);
                }
            }

            const int tn = t + gridDim.x;
            if (tn < nT) ldg8(tn, vb);     // prefetch next A (latency overlaps)

            NBAR_SYNC(4, FTHREADS);        // consumers done with previous ESM
            // store E tile (+bias) to smem ESM
            #pragma unroll
            for (int mt = 0; mt < 2; mt++) {
                #pragma unroll
                for (int nt = 0; nt < 4; nt++) {
                    const int col = wn + nt * 8 + cc;
                    const float b0 = sBias[col], b1 = sBias[col + 1];
                    const int r1 = wm + mt * 16 + cr;
                    float2 o0; o0.x = acc[mt][nt][0] + b0; o0.y = acc[mt][nt][1] + b1;
                    float2 o1; o1.x = acc[mt][nt][2] + b0; o1.y = acc[mt][nt][3] + b1;
                    *(float2*)(smem + FS_ESM + (size_t)(r1 * ESM_STRIDE + col) * 4)       = o0;
                    *(float2*)(smem + FS_ESM + (size_t)((r1 + 8) * ESM_STRIDE + col) * 4) = o1;
                }
            }
            __threadfence_block();
            NBAR_ARRIVE(5, FTHREADS);      // publish ESM(t) to consumers

            // convert next A tile (A reads all done: bar 4 synced producers)
            if (tn < nT) cvt8(vb);
            NBAR_SYNC(1, 512);             // A(t+1) ready for next MMA
        }
    } else {
        // ----------------------- consumers: edge warps -----------------------
        const int cwid = wid - 16;         // 0..3
        const int lid4 = 4 * lid;
        const int h  = lid >> 2;
        const int i4 = lid & 3;

        NBAR_ARRIVE(4, FTHREADS);          // ESM initially free
        for (int t = blockIdx.x; t < nT; t += gridDim.x) {
            NBAR_SYNC(5, FTHREADS);        // wait ESM(t)
            const int e0 = t * 128 + cwid * 32;
            #pragma unroll 1
            for (int b = 0; b < 32; b += 4) {
                int eidx[4], src[4], dst[4];
                #pragma unroll
                for (int i = 0; i < 4; i++) {
                    eidx[i] = e0 + b + i;
                    bool v = eidx[i] < nE;
                    src[i] = v ? __ldg(ei + eidx[i])      : 0;
                    dst[i] = v ? __ldg(ei + nE + eidx[i]) : 0;
                }
                float4 ev[4], kf[4], qf[4], vf[4];
                #pragma unroll
                for (int i = 0; i < 4; i++) {
                    int el = cwid * 32 + b + i;
                    ev[i] = *(const float4*)(smem + FS_ESM + (size_t)(el * ESM_STRIDE + lid4) * 4);
                    kf[i] = *(const float4*)(g_K + (size_t)src[i] * DIM + lid4);
                    qf[i] = *(const float4*)(g_Q + (size_t)dst[i] * DIM + lid4);
                    vf[i] = *(const float4*)(g_V + (size_t)src[i] * DIM + lid4);
                }
                #pragma unroll
                for (int i = 0; i < 4; i++) {
                    if (eidx[i] >= nE) break;
                    float p = kf[i].x * qf[i].x * ev[i].x + kf[i].y * qf[i].y * ev[i].y
                            + kf[i].z * qf[i].z * ev[i].z + kf[i].w * qf[i].w * ev[i].w;
                    p += __shfl_xor_sync(0xFFFFFFFFu, p, 1);
                    p += __shfl_xor_sync(0xFFFFFFFFu, p, 2);
                    p = fminf(fmaxf(p * 0.25f, -5.f), 5.f);
                    const float s = __expf(p);
                    red4(out + (size_t)dst[i] * DIM + lid4,
                         vf[i].x * s, vf[i].y * s, vf[i].z * s, vf[i].w * s);
                    if (i4 == 0) atomicAdd(&g_Z[dst[i] * NH + h], s);
                }
            }
            NBAR_ARRIVE(4, FTHREADS);      // ESM free
        }
    }
}

// ----------------------------- normalize (float4) ---------------------------
__global__ __launch_bounds__(256)
void normalize_kernel(float* __restrict__ out, int n4) {
    int i = blockIdx.x * blockDim.x + threadIdx.x;
    if (i >= n4) return;
    int node = i >> 5;
    int h    = (i >> 2) & 7;
    float z  = g_Z[node * NH + h];
    float inv = 1.0f / (z + 1e-6f);
    float4 o = ((const float4*)out)[i];
    o.x *= inv; o.y *= inv; o.z *= inv; o.w *= inv;
    ((float4*)out)[i] = o;
}

// ----------------------------- launcher -------------------------------------
extern "C" void kernel_launch(void* const* d_in, const int* in_sizes, int n_in,
                              void* d_out, int out_size) {
    const float* x   = (const float*)d_in[0];
    const float* ea  = (const float*)d_in[1];
    const int*   ei  = (const int*)d_in[2];
    const float* Wq  = (const float*)d_in[3];
    const float* bq  = (const float*)d_in[4];
    const float* Wk  = (const float*)d_in[5];
    const float* bk  = (const float*)d_in[6];
    const float* We  = (const float*)d_in[7];
    const float* be  = (const float*)d_in[8];
    const float* Wv  = (const float*)d_in[9];
    const float* bv  = (const float*)d_in[10];
    float* out = (float*)d_out;

    const int nN = in_sizes[0] / DIM;     // 50000
    const int nE = in_sizes[1] / DIM;     // 800000

    float *pQ, *pK, *pV, *pZ;
    __nv_bfloat16 *pW1, *pW2;
    cudaGetSymbolAddress((void**)&pQ, g_Q);
    cudaGetSymbolAddress((void**)&pK, g_K);
    cudaGetSymbolAddress((void**)&pV, g_V);
    cudaGetSymbolAddress((void**)&pZ, g_Z);
    cudaGetSymbolAddress((void**)&pW1, g_W1img);
    cudaGetSymbolAddress((void**)&pW2, g_W2img);

    cudaMemsetAsync(d_out, 0, (size_t)out_size * sizeof(float));
    cudaMemsetAsync(pZ, 0, (size_t)nN * NH * sizeof(float));

    prep_w_kernel<<<(4 * DIM * DIM + 255) / 256, 256>>>(Wq, Wk, Wv, We, pW1, pW2);

    cudaFuncSetAttribute(qkv_gemm_kernel, cudaFuncAttributeMaxDynamicSharedMemorySize, QS_TOTAL);
    cudaFuncSetAttribute(fused_eg_kernel, cudaFuncAttributeMaxDynamicSharedMemorySize, FS_TOTAL);

    int tN = (nN + 127) / 128;    // 391
    int tE = (nE + 127) / 128;    // 6250
    int gN = tN < 148 ? tN : 148;
    qkv_gemm_kernel<<<gN, 512, QS_TOTAL>>>(x, pW1 + 0 * DIM * DIM, pW2 + 0 * DIM * DIM, bq, pQ, nN, tN);
    qkv_gemm_kernel<<<gN, 512, QS_TOTAL>>>(x, pW1 + 1 * DIM * DIM, pW2 + 1 * DIM * DIM, bk, pK, nN, tN);
    qkv_gemm_kernel<<<gN, 512, QS_TOTAL>>>(x, pW1 + 2 * DIM * DIM, pW2 + 2 * DIM * DIM, bv, pV, nN, tN);

    fused_eg_kernel<<<148, FTHREADS, FS_TOTAL>>>(ea, be, ei, out, nE, tE);

    int n4 = nN * DIM / 4;
    normalize_kernel<<<(n4 + 255) / 256, 256>>>(out, n4);
}

// round 14
// speedup vs baseline: 1.2759x; 1.2759x over previous
#include <cuda_runtime.h>
#include <cuda_bf16.h>
#include <math.h>
#include <stdint.h>

// Problem constants (shape-fixed per reference)
#define NN   50000
#define NE_MAX 800000
#define DIM  128
#define NH   8
#define HD   16

// -------- scratch in __device__ globals (no runtime allocation allowed) -----
__device__ float g_Q[NN * DIM];
__device__ float g_K[NN * DIM];
__device__ float g_V[NN * DIM];
__device__ float g_E[(size_t)NE_MAX * DIM];
__device__ float g_Z[NN * NH];
__device__ __nv_bfloat16 g_W1img[4][DIM * DIM];
__device__ __nv_bfloat16 g_W2img[4][DIM * DIM];

// ---------------------------------------------------------------------------
__device__ __forceinline__ uint32_t smem_u32(const void* p) {
    uint32_t a;
    asm("{ .reg .u64 t; cvta.to.shared.u64 t, %1; cvt.u32.u64 %0, t; }"
        : "=r"(a) : "l"(p));
    return a;
}

// Swizzled byte offset inside a [rows x 128] bf16 tile (256B rows).
__device__ __forceinline__ uint32_t soff(int r, int k) {
    uint32_t u = (uint32_t)(k >> 3);
    uint32_t us = (u & 8u) | ((u ^ (uint32_t)(r & 7)) & 7u);
    return (uint32_t)r * 256u + us * 16u + (uint32_t)(k & 7) * 2u;
}

__device__ __forceinline__ void ldsm_x4(uint32_t* r, uint32_t addr) {
    asm("ldmatrix.sync.aligned.m8n8.x4.shared.b16 {%0,%1,%2,%3}, [%4];"
        : "=r"(r[0]), "=r"(r[1]), "=r"(r[2]), "=r"(r[3]) : "r"(addr) : "memory");
}

__device__ __forceinline__ void mma16816(float* d, const uint32_t* a,
                                         uint32_t b0, uint32_t b1) {
    asm("mma.sync.aligned.m16n8k16.row.col.f32.bf16.bf16.f32 "
        "{%0,%1,%2,%3}, {%4,%5,%6,%7}, {%8,%9}, {%0,%1,%2,%3};"
        : "+f"(d[0]), "+f"(d[1]), "+f"(d[2]), "+f"(d[3])
        : "r"(a[0]), "r"(a[1]), "r"(a[2]), "r"(a[3]), "r"(b0), "r"(b1));
}

__device__ __forceinline__ void red4(float* p, float a, float b, float c, float d) {
    asm volatile("red.global.add.v4.f32 [%0], {%1, %2, %3, %4};"
                 :: "l"(p), "f"(a), "f"(b), "f"(c), "f"(d) : "memory");
}

// ---------------- weight prep: fp32 W[k,n] -> swizzled bf16 hi/lo images -----
__global__ __launch_bounds__(256)
void prep_w_kernel(const float* __restrict__ W0, const float* __restrict__ W1,
                   const float* __restrict__ W2, const float* __restrict__ W3,
                   __nv_bfloat16* __restrict__ img1, __nv_bfloat16* __restrict__ img2) {
    int gi = blockIdx.x * 256 + threadIdx.x;
    if (gi >= 4 * DIM * DIM) return;
    int m = gi >> 14;
    int i = gi & (DIM * DIM - 1);
    const float* W = (m == 0) ? W0 : (m == 1) ? W1 : (m == 2) ? W2 : W3;
    int k = i >> 7;
    int n = i & 127;
    float a = W[i];
    __nv_bfloat16 h = __float2bfloat16(a);
    float lo = a - __bfloat162float(h);
    uint32_t off = soff(n, k);
    *(__nv_bfloat16*)((char*)(img1 + (size_t)m * DIM * DIM) + off) = h;
    *(__nv_bfloat16*)((char*)(img2 + (size_t)m * DIM * DIM) + off) = __float2bfloat16(lo);
}

// ----- persistent pipelined HMMA GEMM (the 520us config), tile-ranged -------
// 512 threads, 16 warps in 4(M)x4(N) grid, 32x32 warp tiles, M-tile 128.
// smem: bias 1K | A[2] 128K (each: A1 32K + A2 32K) | W1 32K | W2 32K = 193K
#define SM_BIAS  0
#define SM_ABUF  1024
#define SM_W1    (1024 + 131072)
#define SM_W2    (1024 + 131072 + 32768)
#define SM_TOTAL (1024 + 131072 + 65536)
#define GTHREADS 512

__global__ __launch_bounds__(GTHREADS, 1)
void gemm_mma_kernel(const float* __restrict__ X,
                     const __nv_bfloat16* __restrict__ W1img,
                     const __nv_bfloat16* __restrict__ W2img,
                     const float* __restrict__ bias,
                     float* __restrict__ C, int M, int tStart, int tEnd) {
    extern __shared__ char smem[];
    const uint32_t sb = smem_u32(smem);
    const int tid = threadIdx.x;
    const int wid = tid >> 5;
    const int lid = tid & 31;

    {
        const int4* s1 = (const int4*)W1img;
        const int4* s2 = (const int4*)W2img;
        int4* d1 = (int4*)(smem + SM_W1);
        int4* d2 = (int4*)(smem + SM_W2);
        #pragma unroll
        for (int i = tid; i < 2048; i += GTHREADS) {
            d1[i] = s1[i];
            d2[i] = s2[i];
        }
    }
    if (tid < 128) *(float*)(smem + SM_BIAS + tid * 4) = bias[tid];

    uint32_t preoff[8];
    int      xoff[8];
    #pragma unroll
    for (int w = 0; w < 8; w++) {
        int j  = tid + w * GTHREADS;
        int r  = j >> 5;
        int k4 = (j & 31) << 2;
        preoff[w] = soff(r, k4);
        xoff[w]   = r * DIM + k4;
    }

    auto ldg_wave = [&](int t, int w0, float4* vb) {
        const size_t base = (size_t)t * 128 * DIM;
        const int lim = (M - t * 128) * DIM;
        #pragma unroll
        for (int i = 0; i < 4; i++) {
            int w = w0 + i;
            vb[i] = (xoff[w] < lim) ? *(const float4*)(X + base + xoff[w])
                                    : make_float4(0.f, 0.f, 0.f, 0.f);
        }
    };
    auto cvt_wave = [&](char* abuf, int w0, const float4* vb) {
        #pragma unroll
        for (int i = 0; i < 4; i++) {
            int w = w0 + i;
            float4 v = vb[i];
            __nv_bfloat162 hp0 = __floats2bfloat162_rn(v.x, v.y);
            __nv_bfloat162 hp1 = __floats2bfloat162_rn(v.z, v.w);
            __nv_bfloat162 lp0 = __floats2bfloat162_rn(v.x - __bfloat162float(hp0.x),
                                                       v.y - __bfloat162float(hp0.y));
            __nv_bfloat162 lp1 = __floats2bfloat162_rn(v.z - __bfloat162float(hp1.x),
                                                       v.w - __bfloat162float(hp1.y));
            uint2 hq, lq;
            hq.x = *(uint32_t*)&hp0; hq.y = *(uint32_t*)&hp1;
            lq.x = *(uint32_t*)&lp0; lq.y = *(uint32_t*)&lp1;
            *(uint2*)(abuf + preoff[w])         = hq;
            *(uint2*)(abuf + 32768 + preoff[w]) = lq;
        }
    };

    const int wm = (wid >> 2) * 32;
    const int wn = (wid & 3) * 32;
    const int g  = lid >> 3;
    const int lr = (lid & 7) | ((g & 1) << 3);
    const int kq = (g >> 1) << 3;
    const int cr = lid >> 2;
    const int cc = (lid & 3) * 2;
    const float* sBias = (const float*)(smem + SM_BIAS);

    const int tFirst = tStart + (int)blockIdx.x;
    if (tFirst < tEnd) {
        float4 vb[4];
        ldg_wave(tFirst, 0, vb);
        cvt_wave(smem + SM_ABUF, 0, vb);
        ldg_wave(tFirst, 4, vb);
        cvt_wave(smem + SM_ABUF, 4, vb);
    }
    __syncthreads();

    int pb = 0;
    for (int t = tFirst; t < tEnd; t += gridDim.x, pb ^= 1) {
        const uint32_t cur = sb + SM_ABUF + (uint32_t)pb * 65536u;
        char* nxt = smem + SM_ABUF + (pb ^ 1) * 65536;
        const int tn = t + gridDim.x;
        const bool hn = tn < tEnd;

        float acc[2][4][4];
        #pragma unroll
        for (int i = 0; i < 2; i++)
            #pragma unroll
            for (int j = 0; j < 4; j++)
                #pragma unroll
                for (int u = 0; u < 4; u++) acc[i][j][u] = 0.f;

        float4 vb[4];
        if (hn) ldg_wave(tn, 0, vb);

        #pragma unroll
        for (int half = 0; half < 2; half++) {
            #pragma unroll
            for (int ks = half * 4; ks < half * 4 + 4; ks++) {
                const int k0 = ks * 16 + kq;
                uint32_t a1f[2][4], a2f[2][4], b1f[2][4], b2f[2][4];
                #pragma unroll
                for (int mt = 0; mt < 2; mt++) {
                    ldsm_x4(a1f[mt], cur + soff(wm + mt * 16 + lr, k0));
                    ldsm_x4(a2f[mt], cur + 32768u + soff(wm + mt * 16 + lr, k0));
                }
                #pragma unroll
                for (int nt2 = 0; nt2 < 2; nt2++) {
                    ldsm_x4(b1f[nt2], sb + SM_W1 + soff(wn + nt2 * 16 + lr, k0));
                    ldsm_x4(b2f[nt2], sb + SM_W2 + soff(wn + nt2 * 16 + lr, k0));
                }
                #pragma unroll
                for (int mt = 0; mt < 2; mt++) {
                    mma16816(acc[mt][0], a1f[mt], b1f[0][0], b1f[0][2]);
                    mma16816(acc[mt][1], a1f[mt], b1f[0][1], b1f[0][3]);
                    mma16816(acc[mt][2], a1f[mt], b1f[1][0], b1f[1][2]);
                    mma16816(acc[mt][3], a1f[mt], b1f[1][1], b1f[1][3]);
                }
                #pragma unroll
                for (int mt = 0; mt < 2; mt++) {
                    mma16816(acc[mt][0], a2f[mt], b1f[0][0], b1f[0][2]);
                    mma16816(acc[mt][1], a2f[mt], b1f[0][1], b1f[0][3]);
                    mma16816(acc[mt][2], a2f[mt], b1f[1][0], b1f[1][2]);
                    mma16816(acc[mt][3], a2f[mt], b1f[1][1], b1f[1][3]);
                }
                #pragma unroll
                for (int mt = 0; mt < 2; mt++) {
                    mma16816(acc[mt][0], a1f[mt], b2f[0][0], b2f[0][2]);
                    mma16816(acc[mt][1], a1f[mt], b2f[0][1], b2f[0][3]);
                    mma16816(acc[mt][2], a1f[mt], b2f[1][0], b2f[1][2]);
                    mma16816(acc[mt][3], a1f[mt], b2f[1][1], b2f[1][3]);
                }
            }
            if (hn) {
                cvt_wave(nxt, half * 4, vb);
                if (half == 0) ldg_wave(tn, 4, vb);
            }
        }

        const int row0 = t * 128;
        #pragma unroll
        for (int mt = 0; mt < 2; mt++) {
            #pragma unroll
            for (int nt = 0; nt < 4; nt++) {
                int col = wn + nt * 8 + cc;
                float b0 = sBias[col], b1 = sBias[col + 1];
                int r1 = row0 + wm + mt * 16 + cr;
                if (r1 < M) {
                    float2 o; o.x = acc[mt][nt][0] + b0; o.y = acc[mt][nt][1] + b1;
                    *(float2*)(C + (size_t)r1 * DIM + col) = o;
                }
                int r2 = r1 + 8;
                if (r2 < M) {
                    float2 o; o.x = acc[mt][nt][2] + b0; o.y = acc[mt][nt][3] + b1;
                    *(float2*)(C + (size_t)r2 * DIM + col) = o;
                }
            }
        }
        __syncthreads();
    }
}

// --------------------- edge scatter kernel (edge-ranged) --------------------
__global__ __launch_bounds__(256)
void edge_kernel(const int* __restrict__ ei, const float* __restrict__ E,
                 float* __restrict__ wV, int nE, int e0, int e1) {
    const int lid   = threadIdx.x & 31;
    const int warp  = (blockIdx.x * blockDim.x + threadIdx.x) >> 5;
    const int nwarp = (gridDim.x * blockDim.x) >> 5;
    const int h  = lid >> 2;
    const int i4 = lid & 3;

    for (int e = e0 + warp; e < e1; e += nwarp) {
        int src = __ldg(ei + e);
        int dst = __ldg(ei + nE + e);

        float4 k  = *(const float4*)(g_K + (size_t)src * DIM + 4 * lid);
        float4 q  = *(const float4*)(g_Q + (size_t)dst * DIM + 4 * lid);
        float4 ev = __ldg((const float4*)(E + (size_t)e * DIM + 4 * lid));

        float t = k.x * q.x * ev.x + k.y * q.y * ev.y
                + k.z * q.z * ev.z + k.w * q.w * ev.w;
        t += __shfl_xor_sync(0xFFFFFFFFu, t, 1);
        t += __shfl_xor_sync(0xFFFFFFFFu, t, 2);
        t *= 0.25f;                          // 1/sqrt(16)
        t = fminf(fmaxf(t, -5.f), 5.f);
        float s = __expf(t);

        float4 v = *(const float4*)(g_V + (size_t)src * DIM + 4 * lid);
        red4(wV + (size_t)dst * DIM + 4 * lid, v.x * s, v.y * s, v.z * s, v.w * s);
        if (i4 == 0) atomicAdd(&g_Z[dst * NH + h], s);
    }
}

// ----------------------------- normalize (float4) ---------------------------
__global__ __launch_bounds__(256)
void normalize_kernel(float* __restrict__ out, int n4) {
    int i = blockIdx.x * blockDim.x + threadIdx.x;
    if (i >= n4) return;
    int node = i >> 5;
    int h    = (i >> 2) & 7;
    float z  = g_Z[node * NH + h];
    float inv = 1.0f / (z + 1e-6f);
    float4 o = ((const float4*)out)[i];
    o.x *= inv; o.y *= inv; o.z *= inv; o.w *= inv;
    ((float4*)out)[i] = o;
}

// ----------------------------- launcher -------------------------------------
extern "C" void kernel_launch(void* const* d_in, const int* in_sizes, int n_in,
                              void* d_out, int out_size) {
    const float* x   = (const float*)d_in[0];
    const float* ea  = (const float*)d_in[1];
    const int*   ei  = (const int*)d_in[2];
    const float* Wq  = (const float*)d_in[3];
    const float* bq  = (const float*)d_in[4];
    const float* Wk  = (const float*)d_in[5];
    const float* bk  = (const float*)d_in[6];
    const float* We  = (const float*)d_in[7];
    const float* be  = (const float*)d_in[8];
    const float* Wv  = (const float*)d_in[9];
    const float* bv  = (const float*)d_in[10];
    float* out = (float*)d_out;

    const int nN = in_sizes[0] / DIM;     // 50000
    const int nE = in_sizes[1] / DIM;     // 800000

    float *pQ, *pK, *pV, *pE, *pZ;
    __nv_bfloat16 *pW1, *pW2;
    cudaGetSymbolAddress((void**)&pQ, g_Q);
    cudaGetSymbolAddress((void**)&pK, g_K);
    cudaGetSymbolAddress((void**)&pV, g_V);
    cudaGetSymbolAddress((void**)&pE, g_E);
    cudaGetSymbolAddress((void**)&pZ, g_Z);
    cudaGetSymbolAddress((void**)&pW1, g_W1img);
    cudaGetSymbolAddress((void**)&pW2, g_W2img);

    cudaMemsetAsync(d_out, 0, (size_t)out_size * sizeof(float));
    cudaMemsetAsync(pZ, 0, (size_t)nN * NH * sizeof(float));

    prep_w_kernel<<<(4 * DIM * DIM + 255) / 256, 256>>>(Wq, Wk, Wv, We, pW1, pW2);

    cudaFuncSetAttribute(gemm_mma_kernel, cudaFuncAttributeMaxDynamicSharedMemorySize, SM_TOTAL);

    const int tN = (nN + 127) / 128;    // 391
    const int tE = (nE + 127) / 128;    // 6250
    int gN = tN < 148 ? tN : 148;
    gemm_mma_kernel<<<gN, GTHREADS, SM_TOTAL>>>(x,  pW1 + 0 * DIM * DIM, pW2 + 0 * DIM * DIM, bq, pQ, nN, 0, tN);
    gemm_mma_kernel<<<gN, GTHREADS, SM_TOTAL>>>(x,  pW1 + 1 * DIM * DIM, pW2 + 1 * DIM * DIM, bk, pK, nN, 0, tN);
    gemm_mma_kernel<<<gN, GTHREADS, SM_TOTAL>>>(x,  pW1 + 2 * DIM * DIM, pW2 + 2 * DIM * DIM, bv, pV, nN, 0, tN);

    // Chunked E-GEMM + edge interleave: each edge chunk reads E while it is
    // still L2-resident (chunk E = ~100 MB < 126 MB L2).
    const int NCHUNK = 4;
    const int tPer = (tE + NCHUNK - 1) / NCHUNK;    // 1563 tiles (~200k edges)
    for (int c = 0; c < NCHUNK; c++) {
        int t0 = c * tPer;
        int t1 = (t0 + tPer < tE) ? t0 + tPer : tE;
        if (t0 >= t1) break;
        gemm_mma_kernel<<<148, GTHREADS, SM_TOTAL>>>(ea, pW1 + 3 * DIM * DIM, pW2 + 3 * DIM * DIM,
                                                     be, pE, nE, t0, t1);
        int e0 = t0 * 128;
        int e1 = (t1 * 128 < nE) ? t1 * 128 : nE;
        edge_kernel<<<2048, 256>>>(ei, pE, out, nE, e0, e1);
    }

    int n4 = nN * DIM / 4;
    normalize_kernel<<<(n4 + 255) / 256, 256>>>(out, n4);
}

// round 15
// speedup vs baseline: 1.2945x; 1.0146x over previous
#include <cuda_runtime.h>
#include <cuda_bf16.h>
#include <math.h>
#include <stdint.h>

// Problem constants (shape-fixed per reference)
#define NN   50000
#define NE_MAX 800000
#define DIM  128
#define NH   8
#define HD   16

// -------- scratch in __device__ globals (no runtime allocation allowed) -----
__device__ float g_Q[NN * DIM];
__device__ float g_K[NN * DIM];
__device__ float g_V[NN * DIM];
__device__ float g_E[(size_t)NE_MAX * DIM];
__device__ float g_Z[NN * NH];
__device__ __nv_bfloat16 g_W1img[4][DIM * DIM];
__device__ __nv_bfloat16 g_W2img[4][DIM * DIM];

// ---------------------------------------------------------------------------
__device__ __forceinline__ uint32_t smem_u32(const void* p) {
    uint32_t a;
    asm("{ .reg .u64 t; cvta.to.shared.u64 t, %1; cvt.u32.u64 %0, t; }"
        : "=r"(a) : "l"(p));
    return a;
}

// Swizzled byte offset inside a [rows x 128] bf16 tile (256B rows).
__device__ __forceinline__ uint32_t soff(int r, int k) {
    uint32_t u = (uint32_t)(k >> 3);
    uint32_t us = (u & 8u) | ((u ^ (uint32_t)(r & 7)) & 7u);
    return (uint32_t)r * 256u + us * 16u + (uint32_t)(k & 7) * 2u;
}

__device__ __forceinline__ void ldsm_x4(uint32_t* r, uint32_t addr) {
    asm("ldmatrix.sync.aligned.m8n8.x4.shared.b16 {%0,%1,%2,%3}, [%4];"
        : "=r"(r[0]), "=r"(r[1]), "=r"(r[2]), "=r"(r[3]) : "r"(addr) : "memory");
}

__device__ __forceinline__ void mma16816(float* d, const uint32_t* a,
                                         uint32_t b0, uint32_t b1) {
    asm("mma.sync.aligned.m16n8k16.row.col.f32.bf16.bf16.f32 "
        "{%0,%1,%2,%3}, {%4,%5,%6,%7}, {%8,%9}, {%0,%1,%2,%3};"
        : "+f"(d[0]), "+f"(d[1]), "+f"(d[2]), "+f"(d[3])
        : "r"(a[0]), "r"(a[1]), "r"(a[2]), "r"(a[3]), "r"(b0), "r"(b1));
}

__device__ __forceinline__ void red4(float* p, float a, float b, float c, float d) {
    asm volatile("red.global.add.v4.f32 [%0], {%1, %2, %3, %4};"
                 :: "l"(p), "f"(a), "f"(b), "f"(c), "f"(d) : "memory");
}

// ---------------- weight prep: fp32 W[k,n] -> swizzled bf16 hi/lo images -----
__global__ __launch_bounds__(256)
void prep_w_kernel(const float* __restrict__ W0, const float* __restrict__ W1,
                   const float* __restrict__ W2, const float* __restrict__ W3,
                   __nv_bfloat16* __restrict__ img1, __nv_bfloat16* __restrict__ img2) {
    int gi = blockIdx.x * 256 + threadIdx.x;
    if (gi >= 4 * DIM * DIM) return;
    int m = gi >> 14;
    int i = gi & (DIM * DIM - 1);
    const float* W = (m == 0) ? W0 : (m == 1) ? W1 : (m == 2) ? W2 : W3;
    int k = i >> 7;
    int n = i & 127;
    float a = W[i];
    __nv_bfloat16 h = __float2bfloat16(a);
    float lo = a - __bfloat162float(h);
    uint32_t off = soff(n, k);
    *(__nv_bfloat16*)((char*)(img1 + (size_t)m * DIM * DIM) + off) = h;
    *(__nv_bfloat16*)((char*)(img2 + (size_t)m * DIM * DIM) + off) = __float2bfloat16(lo);
}

// ----- persistent pipelined HMMA GEMM (the 520us config), tile-ranged -------
// 512 threads, 16 warps in 4(M)x4(N) grid, 32x32 warp tiles, M-tile 128.
// smem: bias 1K | A[2] 128K (each: A1 32K + A2 32K) | W1 32K | W2 32K = 193K
#define SM_BIAS  0
#define SM_ABUF  1024
#define SM_W1    (1024 + 131072)
#define SM_W2    (1024 + 131072 + 32768)
#define SM_TOTAL (1024 + 131072 + 65536)
#define GTHREADS 512

__global__ __launch_bounds__(GTHREADS, 1)
void gemm_mma_kernel(const float* __restrict__ X,
                     const __nv_bfloat16* __restrict__ W1img,
                     const __nv_bfloat16* __restrict__ W2img,
                     const float* __restrict__ bias,
                     float* __restrict__ C, int M, int tStart, int tEnd) {
    extern __shared__ char smem[];
    const uint32_t sb = smem_u32(smem);
    const int tid = threadIdx.x;
    const int wid = tid >> 5;
    const int lid = tid & 31;

    {
        const int4* s1 = (const int4*)W1img;
        const int4* s2 = (const int4*)W2img;
        int4* d1 = (int4*)(smem + SM_W1);
        int4* d2 = (int4*)(smem + SM_W2);
        #pragma unroll
        for (int i = tid; i < 2048; i += GTHREADS) {
            d1[i] = s1[i];
            d2[i] = s2[i];
        }
    }
    if (tid < 128) *(float*)(smem + SM_BIAS + tid * 4) = bias[tid];

    uint32_t preoff[8];
    int      xoff[8];
    #pragma unroll
    for (int w = 0; w < 8; w++) {
        int j  = tid + w * GTHREADS;
        int r  = j >> 5;
        int k4 = (j & 31) << 2;
        preoff[w] = soff(r, k4);
        xoff[w]   = r * DIM + k4;
    }

    auto ldg_wave = [&](int t, int w0, float4* vb) {
        const size_t base = (size_t)t * 128 * DIM;
        const int lim = (M - t * 128) * DIM;
        #pragma unroll
        for (int i = 0; i < 4; i++) {
            int w = w0 + i;
            vb[i] = (xoff[w] < lim) ? *(const float4*)(X + base + xoff[w])
                                    : make_float4(0.f, 0.f, 0.f, 0.f);
        }
    };
    auto cvt_wave = [&](char* abuf, int w0, const float4* vb) {
        #pragma unroll
        for (int i = 0; i < 4; i++) {
            int w = w0 + i;
            float4 v = vb[i];
            __nv_bfloat162 hp0 = __floats2bfloat162_rn(v.x, v.y);
            __nv_bfloat162 hp1 = __floats2bfloat162_rn(v.z, v.w);
            __nv_bfloat162 lp0 = __floats2bfloat162_rn(v.x - __bfloat162float(hp0.x),
                                                       v.y - __bfloat162float(hp0.y));
            __nv_bfloat162 lp1 = __floats2bfloat162_rn(v.z - __bfloat162float(hp1.x),
                                                       v.w - __bfloat162float(hp1.y));
            uint2 hq, lq;
            hq.x = *(uint32_t*)&hp0; hq.y = *(uint32_t*)&hp1;
            lq.x = *(uint32_t*)&lp0; lq.y = *(uint32_t*)&lp1;
            *(uint2*)(abuf + preoff[w])         = hq;
            *(uint2*)(abuf + 32768 + preoff[w]) = lq;
        }
    };

    const int wm = (wid >> 2) * 32;
    const int wn = (wid & 3) * 32;
    const int g  = lid >> 3;
    const int lr = (lid & 7) | ((g & 1) << 3);
    const int kq = (g >> 1) << 3;
    const int cr = lid >> 2;
    const int cc = (lid & 3) * 2;
    const float* sBias = (const float*)(smem + SM_BIAS);

    const int tFirst = tStart + (int)blockIdx.x;
    if (tFirst < tEnd) {
        float4 vb[4];
        ldg_wave(tFirst, 0, vb);
        cvt_wave(smem + SM_ABUF, 0, vb);
        ldg_wave(tFirst, 4, vb);
        cvt_wave(smem + SM_ABUF, 4, vb);
    }
    __syncthreads();

    int pb = 0;
    for (int t = tFirst; t < tEnd; t += gridDim.x, pb ^= 1) {
        const uint32_t cur = sb + SM_ABUF + (uint32_t)pb * 65536u;
        char* nxt = smem + SM_ABUF + (pb ^ 1) * 65536;
        const int tn = t + gridDim.x;
        const bool hn = tn < tEnd;

        float acc[2][4][4];
        #pragma unroll
        for (int i = 0; i < 2; i++)
            #pragma unroll
            for (int j = 0; j < 4; j++)
                #pragma unroll
                for (int u = 0; u < 4; u++) acc[i][j][u] = 0.f;

        float4 vb[4];
        if (hn) ldg_wave(tn, 0, vb);

        #pragma unroll
        for (int half = 0; half < 2; half++) {
            #pragma unroll
            for (int ks = half * 4; ks < half * 4 + 4; ks++) {
                const int k0 = ks * 16 + kq;
                uint32_t a1f[2][4], a2f[2][4], b1f[2][4], b2f[2][4];
                #pragma unroll
                for (int mt = 0; mt < 2; mt++) {
                    ldsm_x4(a1f[mt], cur + soff(wm + mt * 16 + lr, k0));
                    ldsm_x4(a2f[mt], cur + 32768u + soff(wm + mt * 16 + lr, k0));
                }
                #pragma unroll
                for (int nt2 = 0; nt2 < 2; nt2++) {
                    ldsm_x4(b1f[nt2], sb + SM_W1 + soff(wn + nt2 * 16 + lr, k0));
                    ldsm_x4(b2f[nt2], sb + SM_W2 + soff(wn + nt2 * 16 + lr, k0));
                }
                #pragma unroll
                for (int mt = 0; mt < 2; mt++) {
                    mma16816(acc[mt][0], a1f[mt], b1f[0][0], b1f[0][2]);
                    mma16816(acc[mt][1], a1f[mt], b1f[0][1], b1f[0][3]);
                    mma16816(acc[mt][2], a1f[mt], b1f[1][0], b1f[1][2]);
                    mma16816(acc[mt][3], a1f[mt], b1f[1][1], b1f[1][3]);
                }
                #pragma unroll
                for (int mt = 0; mt < 2; mt++) {
                    mma16816(acc[mt][0], a2f[mt], b1f[0][0], b1f[0][2]);
                    mma16816(acc[mt][1], a2f[mt], b1f[0][1], b1f[0][3]);
                    mma16816(acc[mt][2], a2f[mt], b1f[1][0], b1f[1][2]);
                    mma16816(acc[mt][3], a2f[mt], b1f[1][1], b1f[1][3]);
                }
                #pragma unroll
                for (int mt = 0; mt < 2; mt++) {
                    mma16816(acc[mt][0], a1f[mt], b2f[0][0], b2f[0][2]);
                    mma16816(acc[mt][1], a1f[mt], b2f[0][1], b2f[0][3]);
                    mma16816(acc[mt][2], a1f[mt], b2f[1][0], b2f[1][2]);
                    mma16816(acc[mt][3], a1f[mt], b2f[1][1], b2f[1][3]);
                }
            }
            if (hn) {
                cvt_wave(nxt, half * 4, vb);
                if (half == 0) ldg_wave(tn, 4, vb);
            }
        }

        const int row0 = t * 128;
        #pragma unroll
        for (int mt = 0; mt < 2; mt++) {
            #pragma unroll
            for (int nt = 0; nt < 4; nt++) {
                int col = wn + nt * 8 + cc;
                float b0 = sBias[col], b1 = sBias[col + 1];
                int r1 = row0 + wm + mt * 16 + cr;
                if (r1 < M) {
                    float2 o; o.x = acc[mt][nt][0] + b0; o.y = acc[mt][nt][1] + b1;
                    *(float2*)(C + (size_t)r1 * DIM + col) = o;
                }
                int r2 = r1 + 8;
                if (r2 < M) {
                    float2 o; o.x = acc[mt][nt][2] + b0; o.y = acc[mt][nt][3] + b1;
                    *(float2*)(C + (size_t)r2 * DIM + col) = o;
                }
            }
        }
        __syncthreads();
    }
}

// --------------------- edge scatter kernel (edge-ranged) --------------------
__global__ __launch_bounds__(256)
void edge_kernel(const int* __restrict__ ei, const float* __restrict__ E,
                 float* __restrict__ wV, int nE, int e0, int e1) {
    const int lid   = threadIdx.x & 31;
    const int warp  = (blockIdx.x * blockDim.x + threadIdx.x) >> 5;
    const int nwarp = (gridDim.x * blockDim.x) >> 5;
    const int h  = lid >> 2;
    const int i4 = lid & 3;

    for (int e = e0 + warp; e < e1; e += nwarp) {
        int src = __ldg(ei + e);
        int dst = __ldg(ei + nE + e);

        float4 k  = *(const float4*)(g_K + (size_t)src * DIM + 4 * lid);
        float4 q  = *(const float4*)(g_Q + (size_t)dst * DIM + 4 * lid);
        float4 ev = __ldg((const float4*)(E + (size_t)e * DIM + 4 * lid));

        float t = k.x * q.x * ev.x + k.y * q.y * ev.y
                + k.z * q.z * ev.z + k.w * q.w * ev.w;
        t += __shfl_xor_sync(0xFFFFFFFFu, t, 1);
        t += __shfl_xor_sync(0xFFFFFFFFu, t, 2);
        t *= 0.25f;                          // 1/sqrt(16)
        t = fminf(fmaxf(t, -5.f), 5.f);
        float s = __expf(t);

        float4 v = *(const float4*)(g_V + (size_t)src * DIM + 4 * lid);
        red4(wV + (size_t)dst * DIM + 4 * lid, v.x * s, v.y * s, v.z * s, v.w * s);
        if (i4 == 0) atomicAdd(&g_Z[dst * NH + h], s);
    }
}

// ----------------------------- normalize (float4) ---------------------------
__global__ __launch_bounds__(256)
void normalize_kernel(float* __restrict__ out, int n4) {
    int i = blockIdx.x * blockDim.x + threadIdx.x;
    if (i >= n4) return;
    int node = i >> 5;
    int h    = (i >> 2) & 7;
    float z  = g_Z[node * NH + h];
    float inv = 1.0f / (z + 1e-6f);
    float4 o = ((const float4*)out)[i];
    o.x *= inv; o.y *= inv; o.z *= inv; o.w *= inv;
    ((float4*)out)[i] = o;
}

// ----------------------------- launcher -------------------------------------
#define NCHUNK 4

extern "C" void kernel_launch(void* const* d_in, const int* in_sizes, int n_in,
                              void* d_out, int out_size) {
    const float* x   = (const float*)d_in[0];
    const float* ea  = (const float*)d_in[1];
    const int*   ei  = (const int*)d_in[2];
    const float* Wq  = (const float*)d_in[3];
    const float* bq  = (const float*)d_in[4];
    const float* Wk  = (const float*)d_in[5];
    const float* bk  = (const float*)d_in[6];
    const float* We  = (const float*)d_in[7];
    const float* be  = (const float*)d_in[8];
    const float* Wv  = (const float*)d_in[9];
    const float* bv  = (const float*)d_in[10];
    float* out = (float*)d_out;

    const int nN = in_sizes[0] / DIM;     // 50000
    const int nE = in_sizes[1] / DIM;     // 800000

    // One-time resources (created on the uncaptured correctness call; reused
    // every call — same launches/deps every time, fully deterministic).
    static cudaStream_t sEdge = nullptr;
    static cudaEvent_t  evG[NCHUNK];
    static cudaEvent_t  evJoin;
    if (!sEdge) {
        cudaStreamCreateWithFlags(&sEdge, cudaStreamNonBlocking);
        for (int c = 0; c < NCHUNK; c++)
            cudaEventCreateWithFlags(&evG[c], cudaEventDisableTiming);
        cudaEventCreateWithFlags(&evJoin, cudaEventDisableTiming);
    }

    float *pQ, *pK, *pV, *pE, *pZ;
    __nv_bfloat16 *pW1, *pW2;
    cudaGetSymbolAddress((void**)&pQ, g_Q);
    cudaGetSymbolAddress((void**)&pK, g_K);
    cudaGetSymbolAddress((void**)&pV, g_V);
    cudaGetSymbolAddress((void**)&pE, g_E);
    cudaGetSymbolAddress((void**)&pZ, g_Z);
    cudaGetSymbolAddress((void**)&pW1, g_W1img);
    cudaGetSymbolAddress((void**)&pW2, g_W2img);

    cudaMemsetAsync(d_out, 0, (size_t)out_size * sizeof(float));
    cudaMemsetAsync(pZ, 0, (size_t)nN * NH * sizeof(float));

    prep_w_kernel<<<(4 * DIM * DIM + 255) / 256, 256>>>(Wq, Wk, Wv, We, pW1, pW2);

    cudaFuncSetAttribute(gemm_mma_kernel, cudaFuncAttributeMaxDynamicSharedMemorySize, SM_TOTAL);

    const int tN = (nN + 127) / 128;    // 391
    const int tE = (nE + 127) / 128;    // 6250
    int gN = tN < 148 ? tN : 148;
    gemm_mma_kernel<<<gN, GTHREADS, SM_TOTAL>>>(x,  pW1 + 0 * DIM * DIM, pW2 + 0 * DIM * DIM, bq, pQ, nN, 0, tN);
    gemm_mma_kernel<<<gN, GTHREADS, SM_TOTAL>>>(x,  pW1 + 1 * DIM * DIM, pW2 + 1 * DIM * DIM, bk, pK, nN, 0, tN);
    gemm_mma_kernel<<<gN, GTHREADS, SM_TOTAL>>>(x,  pW1 + 2 * DIM * DIM, pW2 + 2 * DIM * DIM, bv, pV, nN, 0, tN);

    // Pipelined E-GEMM (stream 0) + edge scatter (sEdge): edge chunk c runs
    // concurrently with E-GEMM chunk c+1. Complementary bottlenecks (tensor
    // vs DRAM) and L2-warm E (chunk ~100 MB < 126 MB L2).
    const int tPer = (tE + NCHUNK - 1) / NCHUNK;
    for (int c = 0; c < NCHUNK; c++) {
        int t0 = c * tPer;
        int t1 = (t0 + tPer < tE) ? t0 + tPer : tE;
        if (t0 >= t1) break;
        gemm_mma_kernel<<<148, GTHREADS, SM_TOTAL>>>(ea, pW1 + 3 * DIM * DIM, pW2 + 3 * DIM * DIM,
                                                     be, pE, nE, t0, t1);
        cudaEventRecord(evG[c], 0);
        cudaStreamWaitEvent(sEdge, evG[c], 0);
        int e0 = t0 * 128;
        int e1 = (t1 * 128 < nE) ? t1 * 128 : nE;
        edge_kernel<<<2048, 256, 0, sEdge>>>(ei, pE, out, nE, e0, e1);
    }
    cudaEventRecord(evJoin, sEdge);
    cudaStreamWaitEvent(0, evJoin, 0);

    int n4 = nN * DIM / 4;
    normalize_kernel<<<(n4 + 255) / 256, 256>>>(out, n4);
}

// round 16
// speedup vs baseline: 1.4755x; 1.1398x over previous
#include <cuda_runtime.h>
#include <cuda_bf16.h>
#include <math.h>
#include <stdint.h>

// Problem constants (shape-fixed per reference)
#define NN   50000
#define NE_MAX 800000
#define DIM  128
#define NH   8
#define HD   16

// -------- scratch in __device__ globals (no runtime allocation allowed) -----
__device__ float g_Q[NN * DIM];
__device__ float g_K[NN * DIM];
__device__ float g_V[NN * DIM];
__device__ float g_E[(size_t)NE_MAX * DIM];
__device__ float g_Z[NN * NH];
// tf32 weight images in fragment-paired layout: [4][128 n-rows][136 words]
#define WROW 136
__device__ float g_Wimg[4][DIM * WROW];

// ---------------------------------------------------------------------------
__device__ __forceinline__ uint32_t f2tf32(float x) {
    uint32_t r;
    asm("cvt.rna.tf32.f32 %0, %1;" : "=r"(r) : "f"(x));
    return r;
}

// word (float) offset inside a [rows][136] paired tile for element (row, k):
// pair = (k, k+4) within each k8 block; word = row*136 + (k>>3)*8 + (k&3)*2 + ((k>>2)&1)
__host__ __device__ __forceinline__ int pword(int row, int k) {
    return row * WROW + ((k >> 3) << 3) + ((k & 3) << 1) + ((k >> 2) & 1);
}

__device__ __forceinline__ void mma_tf32(float* d, uint32_t a0, uint32_t a1,
                                         uint32_t a2, uint32_t a3,
                                         uint32_t b0, uint32_t b1) {
    asm("mma.sync.aligned.m16n8k8.row.col.f32.tf32.tf32.f32 "
        "{%0,%1,%2,%3}, {%4,%5,%6,%7}, {%8,%9}, {%0,%1,%2,%3};"
        : "+f"(d[0]), "+f"(d[1]), "+f"(d[2]), "+f"(d[3])
        : "r"(a0), "r"(a1), "r"(a2), "r"(a3), "r"(b0), "r"(b1));
}

__device__ __forceinline__ void red4(float* p, float a, float b, float c, float d) {
    asm volatile("red.global.add.v4.f32 [%0], {%1, %2, %3, %4};"
                 :: "l"(p), "f"(a), "f"(b), "f"(c), "f"(d) : "memory");
}

// ---------------- weight prep: fp32 W[k,n] -> paired tf32 images ------------
__global__ __launch_bounds__(256)
void prep_w_kernel(const float* __restrict__ W0, const float* __restrict__ W1,
                   const float* __restrict__ W2, const float* __restrict__ W3) {
    int gi = blockIdx.x * 256 + threadIdx.x;
    if (gi >= 4 * DIM * DIM) return;
    int m = gi >> 14;
    int i = gi & (DIM * DIM - 1);
    const float* W = (m == 0) ? W0 : (m == 1) ? W1 : (m == 2) ? W2 : W3;
    int k = i >> 7;
    int n = i & 127;
    uint32_t v = f2tf32(W[i]);
    *(uint32_t*)&g_Wimg[m][pword(n, k)] = v;
}

// ------- persistent pipelined tf32 GEMM: C[M,128] = X[M,128]@W + b ----------
// 512 threads, 16 warps in 4(M)x4(N) grid, 32x32 warp tiles, M-tile 128.
// smem (floats): bias 1K | A[2] paired tf32 (each 128x136 = 69.6K) | W 69.6K
#define SM_BIAS  0
#define SM_ABUF  1024
#define ABYTES   (128 * WROW * 4)
#define SM_W     (SM_ABUF + 2 * ABYTES)
#define SM_TOTAL (SM_W + ABYTES)
#define GTHREADS 512

__global__ __launch_bounds__(GTHREADS, 1)
void gemm_tf32_kernel(const float* __restrict__ X,
                      const float* __restrict__ Wimg,
                      const float* __restrict__ bias,
                      float* __restrict__ C, int M, int nT) {
    extern __shared__ char smem[];
    float* smf = (float*)smem;
    const int tid = threadIdx.x;
    const int wid = tid >> 5;
    const int lid = tid & 31;

    // ---- one-time: weight image + bias into smem (linear copy) ----
    {
        const int4* s = (const int4*)Wimg;
        int4* d = (int4*)(smem + SM_W);
        #pragma unroll
        for (int i = tid; i < ABYTES / 16; i += GTHREADS) d[i] = s[i];
    }
    if (tid < 128) smf[SM_BIAS / 4 + tid] = bias[tid];

    // ---- per-thread convert slots: j = tid + w*512 -> (r = j>>5, cl = j&31),
    //      c = cl + 32*q (q=0..3). woff + 32*q addresses the paired layout. ----
    int rj[8], cj[8], woff[8];
    #pragma unroll
    for (int w = 0; w < 8; w++) {
        int j  = tid + w * GTHREADS;
        rj[w] = j >> 5;
        cj[w] = j & 31;
        woff[w] = rj[w] * WROW + ((cj[w] >> 3) << 3) + ((cj[w] & 3) << 1)
                + ((cj[w] >> 2) & 1);
    }

    auto ldg_wave = [&](int t, int w0, float4* vb) {
        const size_t base = (size_t)t * 128 * DIM;
        const int lim = (M - t * 128) * DIM;
        #pragma unroll
        for (int i = 0; i < 4; i++) {
            int w = w0 + i;
            int x0 = rj[w] * DIM + cj[w];
            float4 v;
            v.x = (x0 +  0 < lim) ? X[base + x0 +  0] : 0.f;
            v.y = (x0 + 32 < lim) ? X[base + x0 + 32] : 0.f;
            v.z = (x0 + 64 < lim) ? X[base + x0 + 64] : 0.f;
            v.w = (x0 + 96 < lim) ? X[base + x0 + 96] : 0.f;
            vb[i] = v;
        }
    };
    auto cvt_wave = [&](float* abuf, int w0, const float4* vb) {
        #pragma unroll
        for (int i = 0; i < 4; i++) {
            int w = w0 + i;
            uint32_t* p = (uint32_t*)(abuf + woff[w]);
            p[0]  = f2tf32(vb[i].x);
            p[32] = f2tf32(vb[i].y);
            p[64] = f2tf32(vb[i].z);
            p[96] = f2tf32(vb[i].w);
        }
    };

    const int wm = (wid >> 2) * 32;
    const int wn = (wid & 3) * 32;
    const int g  = lid >> 2;          // 0..7
    const int kk = lid & 3;
    const int cr = lid >> 2;
    const int cc = (lid & 3) * 2;
    const float* sBias = smf + SM_BIAS / 4;
    float* W = smf + SM_W / 4;

    if ((int)blockIdx.x < nT) {
        float4 vb[4];
        ldg_wave(blockIdx.x, 0, vb);
        cvt_wave(smf + SM_ABUF / 4, 0, vb);
        ldg_wave(blockIdx.x, 4, vb);
        cvt_wave(smf + SM_ABUF / 4, 4, vb);
    }
    __syncthreads();

    // per-warp fragment base word offsets (without kstep term)
    const int aBase0 = (wm + g) * WROW + kk * 2;           // rows g (mt adds 16*WROW)
    int bBase[4];
    #pragma unroll
    for (int nt = 0; nt < 4; nt++)
        bBase[nt] = (wn + nt * 8 + g) * WROW + kk * 2;

    int pb = 0;
    for (int t = blockIdx.x; t < nT; t += gridDim.x, pb ^= 1) {
        float* cur = smf + SM_ABUF / 4 + pb * (ABYTES / 4);
        float* nxt = smf + SM_ABUF / 4 + (pb ^ 1) * (ABYTES / 4);
        const int tn = t + gridDim.x;
        const bool hn = tn < nT;

        float acc[2][4][4];
        #pragma unroll
        for (int i = 0; i < 2; i++)
            #pragma unroll
            for (int j = 0; j < 4; j++)
                #pragma unroll
                for (int u = 0; u < 4; u++) acc[i][j][u] = 0.f;

        float4 vb[4];
        if (hn) ldg_wave(tn, 0, vb);

        #pragma unroll
        for (int half = 0; half < 2; half++) {
            #pragma unroll
            for (int ks = half * 8; ks < half * 8 + 8; ks++) {
                const int ko = ks * 8;
                // A frags: mt 0/1, rows (g | g+8): LDS.64 pairs {col kk, kk+4}
                uint2 aLo[2], aHi[2];
                #pragma unroll
                for (int mt = 0; mt < 2; mt++) {
                    aLo[mt] = *(const uint2*)(cur + aBase0 + mt * 16 * WROW + ko);
                    aHi[mt] = *(const uint2*)(cur + aBase0 + mt * 16 * WROW + 8 * WROW + ko);
                }
                uint2 bf[4];
                #pragma unroll
                for (int nt = 0; nt < 4; nt++)
                    bf[nt] = *(const uint2*)(W + bBase[nt] + ko);
                #pragma unroll
                for (int mt = 0; mt < 2; mt++) {
                    mma_tf32(acc[mt][0], aLo[mt].x, aHi[mt].x, aLo[mt].y, aHi[mt].y,
                             bf[0].x, bf[0].y);
                    mma_tf32(acc[mt][1], aLo[mt].x, aHi[mt].x, aLo[mt].y, aHi[mt].y,
                             bf[1].x, bf[1].y);
                    mma_tf32(acc[mt][2], aLo[mt].x, aHi[mt].x, aLo[mt].y, aHi[mt].y,
                             bf[2].x, bf[2].y);
                    mma_tf32(acc[mt][3], aLo[mt].x, aHi[mt].x, aLo[mt].y, aHi[mt].y,
                             bf[3].x, bf[3].y);
                }
            }
            if (hn) {
                cvt_wave(nxt, half * 4, vb);
                if (half == 0) ldg_wave(tn, 4, vb);
            }
        }

        // epilogue (c-frag layout: rows cr / cr+8, cols cc, cc+1)
        const int row0 = t * 128;
        #pragma unroll
        for (int mt = 0; mt < 2; mt++) {
            #pragma unroll
            for (int nt = 0; nt < 4; nt++) {
                int col = wn + nt * 8 + cc;
                float b0 = sBias[col], b1 = sBias[col + 1];
                int r1 = row0 + wm + mt * 16 + cr;
                if (r1 < M) {
                    float2 o; o.x = acc[mt][nt][0] + b0; o.y = acc[mt][nt][1] + b1;
                    *(float2*)(C + (size_t)r1 * DIM + col) = o;
                }
                int r2 = r1 + 8;
                if (r2 < M) {
                    float2 o; o.x = acc[mt][nt][2] + b0; o.y = acc[mt][nt][3] + b1;
                    *(float2*)(C + (size_t)r2 * DIM + col) = o;
                }
            }
        }
        __syncthreads();
    }
}

// --------------------------- edge scatter kernel ----------------------------
__global__ __launch_bounds__(256)
void edge_kernel(const int* __restrict__ ei, const float* __restrict__ E,
                 float* __restrict__ wV, int nE) {
    const int lid   = threadIdx.x & 31;
    const int warp  = (blockIdx.x * blockDim.x + threadIdx.x) >> 5;
    const int nwarp = (gridDim.x * blockDim.x) >> 5;
    const int h  = lid >> 2;
    const int i4 = lid & 3;

    for (int e = warp; e < nE; e += nwarp) {
        int src = __ldg(ei + e);
        int dst = __ldg(ei + nE + e);

        float4 k  = *(const float4*)(g_K + (size_t)src * DIM + 4 * lid);
        float4 q  = *(const float4*)(g_Q + (size_t)dst * DIM + 4 * lid);
        float4 ev = __ldg((const float4*)(E + (size_t)e * DIM + 4 * lid));

        float t = k.x * q.x * ev.x + k.y * q.y * ev.y
                + k.z * q.z * ev.z + k.w * q.w * ev.w;
        t += __shfl_xor_sync(0xFFFFFFFFu, t, 1);
        t += __shfl_xor_sync(0xFFFFFFFFu, t, 2);
        t *= 0.25f;                          // 1/sqrt(16)
        t = fminf(fmaxf(t, -5.f), 5.f);
        float s = __expf(t);

        float4 v = *(const float4*)(g_V + (size_t)src * DIM + 4 * lid);
        red4(wV + (size_t)dst * DIM + 4 * lid, v.x * s, v.y * s, v.z * s, v.w * s);
        if (i4 == 0) atomicAdd(&g_Z[dst * NH + h], s);
    }
}

// ----------------------------- normalize (float4) ---------------------------
__global__ __launch_bounds__(256)
void normalize_kernel(float* __restrict__ out, int n4) {
    int i = blockIdx.x * blockDim.x + threadIdx.x;
    if (i >= n4) return;
    int node = i >> 5;
    int h    = (i >> 2) & 7;
    float z  = g_Z[node * NH + h];
    float inv = 1.0f / (z + 1e-6f);
    float4 o = ((const float4*)out)[i];
    o.x *= inv; o.y *= inv; o.z *= inv; o.w *= inv;
    ((float4*)out)[i] = o;
}

// ----------------------------- launcher -------------------------------------
extern "C" void kernel_launch(void* const* d_in, const int* in_sizes, int n_in,
                              void* d_out, int out_size) {
    const float* x   = (const float*)d_in[0];
    const float* ea  = (const float*)d_in[1];
    const int*   ei  = (const int*)d_in[2];
    const float* Wq  = (const float*)d_in[3];
    const float* bq  = (const float*)d_in[4];
    const float* Wk  = (const float*)d_in[5];
    const float* bk  = (const float*)d_in[6];
    const float* We  = (const float*)d_in[7];
    const float* be  = (const float*)d_in[8];
    const float* Wv  = (const float*)d_in[9];
    const float* bv  = (const float*)d_in[10];
    float* out = (float*)d_out;

    const int nN = in_sizes[0] / DIM;     // 50000
    const int nE = in_sizes[1] / DIM;     // 800000

    float *pQ, *pK, *pV, *pE, *pZ, *pW;
    cudaGetSymbolAddress((void**)&pQ, g_Q);
    cudaGetSymbolAddress((void**)&pK, g_K);
    cudaGetSymbolAddress((void**)&pV, g_V);
    cudaGetSymbolAddress((void**)&pE, g_E);
    cudaGetSymbolAddress((void**)&pZ, g_Z);
    cudaGetSymbolAddress((void**)&pW, g_Wimg);

    cudaMemsetAsync(d_out, 0, (size_t)out_size * sizeof(float));
    cudaMemsetAsync(pZ, 0, (size_t)nN * NH * sizeof(float));

    prep_w_kernel<<<(4 * DIM * DIM + 255) / 256, 256>>>(Wq, Wk, Wv, We);

    cudaFuncSetAttribute(gemm_tf32_kernel, cudaFuncAttributeMaxDynamicSharedMemorySize, SM_TOTAL);

    const int tN = (nN + 127) / 128;    // 391
    const int tE = (nE + 127) / 128;    // 6250
    int gN = tN < 148 ? tN : 148;
    gemm_tf32_kernel<<<gN, GTHREADS, SM_TOTAL>>>(x,  pW + 0 * DIM * WROW, bq, pQ, nN, tN);
    gemm_tf32_kernel<<<gN, GTHREADS, SM_TOTAL>>>(x,  pW + 1 * DIM * WROW, bk, pK, nN, tN);
    gemm_tf32_kernel<<<gN, GTHREADS, SM_TOTAL>>>(x,  pW + 2 * DIM * WROW, bv, pV, nN, tN);
    gemm_tf32_kernel<<<148, GTHREADS, SM_TOTAL>>>(ea, pW + 3 * DIM * WROW, be, pE, nE, tE);

    edge_kernel<<<4096, 256>>>(ei, pE, out, nE);

    int n4 = nN * DIM / 4;
    normalize_kernel<<<(n4 + 255) / 256, 256>>>(out, n4);
}

// round 17
// speedup vs baseline: 1.5060x; 1.0207x over previous
#include <cuda_runtime.h>
#include <cuda_bf16.h>
#include <math.h>
#include <stdint.h>

// Problem constants (shape-fixed per reference)
#define NN   50000
#define NE_MAX 800000
#define DIM  128
#define NH   8
#define HD   16

// -------- scratch in __device__ globals (no runtime allocation allowed) -----
__device__ float g_Q[NN * DIM];
__device__ float g_K[NN * DIM];
__device__ float g_V[NN * DIM];
__device__ float g_E[(size_t)NE_MAX * DIM];
__device__ float g_Z[NN * NH];
// tf32 weight images in fragment-paired layout: [4][128 n-rows][136 words]
#define WROW 136
__device__ float g_Wimg[4][DIM * WROW];

// ---------------------------------------------------------------------------
__device__ __forceinline__ uint32_t f2tf32(float x) {
    uint32_t r;
    asm("cvt.rna.tf32.f32 %0, %1;" : "=r"(r) : "f"(x));
    return r;
}

// word (float) offset inside a [rows][136] paired tile for element (row, k)
__host__ __device__ __forceinline__ int pword(int row, int k) {
    return row * WROW + ((k >> 3) << 3) + ((k & 3) << 1) + ((k >> 2) & 1);
}

__device__ __forceinline__ void mma_tf32(float* d, uint32_t a0, uint32_t a1,
                                         uint32_t a2, uint32_t a3,
                                         uint32_t b0, uint32_t b1) {
    asm("mma.sync.aligned.m16n8k8.row.col.f32.tf32.tf32.f32 "
        "{%0,%1,%2,%3}, {%4,%5,%6,%7}, {%8,%9}, {%0,%1,%2,%3};"
        : "+f"(d[0]), "+f"(d[1]), "+f"(d[2]), "+f"(d[3])
        : "r"(a0), "r"(a1), "r"(a2), "r"(a3), "r"(b0), "r"(b1));
}

__device__ __forceinline__ void red4(float* p, float a, float b, float c, float d) {
    asm volatile("red.global.add.v4.f32 [%0], {%1, %2, %3, %4};"
                 :: "l"(p), "f"(a), "f"(b), "f"(c), "f"(d) : "memory");
}

// ---------------- weight prep: fp32 W[k,n] -> paired tf32 images ------------
__global__ __launch_bounds__(256)
void prep_w_kernel(const float* __restrict__ W0, const float* __restrict__ W1,
                   const float* __restrict__ W2, const float* __restrict__ W3) {
    int gi = blockIdx.x * 256 + threadIdx.x;
    if (gi >= 4 * DIM * DIM) return;
    int m = gi >> 14;
    int i = gi & (DIM * DIM - 1);
    const float* W = (m == 0) ? W0 : (m == 1) ? W1 : (m == 2) ? W2 : W3;
    int k = i >> 7;
    int n = i & 127;
    uint32_t v = f2tf32(W[i]);
    *(uint32_t*)&g_Wimg[m][pword(n, k)] = v;
}

// ------- persistent pipelined tf32 GEMM machinery ---------------------------
// 512 threads, 16 warps in 4(M)x4(N) grid, 32x32 warp tiles, M-tile 128.
// smem (floats): bias 1K | A[2] paired tf32 (each 128x136 = 69.6K) | W 69.6K
#define SM_BIAS  0
#define SM_ABUF  1024
#define ABYTES   (128 * WROW * 4)
#define SM_W     (SM_ABUF + 2 * ABYTES)
#define SM_TOTAL (SM_W + ABYTES)
#define GTHREADS 512

// Shared device-side body pieces are expressed inline in each kernel (the two
// kernels differ in output/W selection logic only).

// -------------------- fused QKV GEMM: one launch, m-major tiles -------------
__global__ __launch_bounds__(GTHREADS, 1)
void qkv_fused_kernel(const float* __restrict__ X,
                      const float* __restrict__ bq, const float* __restrict__ bk,
                      const float* __restrict__ bv,
                      float* __restrict__ Cq, float* __restrict__ Ck,
                      float* __restrict__ Cv, int M, int nT) {
    extern __shared__ char smem[];
    float* smf = (float*)smem;
    const int tid = threadIdx.x;
    const int wid = tid >> 5;
    const int lid = tid & 31;
    const int nTot = 3 * nT;

    // per-thread convert slots
    int rj[8], cj[8], woff[8];
    #pragma unroll
    for (int w = 0; w < 8; w++) {
        int j  = tid + w * GTHREADS;
        rj[w] = j >> 5;
        cj[w] = j & 31;
        woff[w] = rj[w] * WROW + ((cj[w] >> 3) << 3) + ((cj[w] & 3) << 1)
                + ((cj[w] >> 2) & 1);
    }

    auto loadW = [&](int m) {
        const int4* s = (const int4*)(g_Wimg[m]);
        int4* d = (int4*)(smem + SM_W);
        #pragma unroll
        for (int i = tid; i < ABYTES / 16; i += GTHREADS) d[i] = s[i];
        const float* b = (m == 0) ? bq : (m == 1) ? bk : bv;
        if (tid < 128) smf[SM_BIAS / 4 + tid] = b[tid];
    };

    auto ldg_wave = [&](int tile, int w0, float4* vb) {
        const size_t base = (size_t)tile * 128 * DIM;
        const int lim = (M - tile * 128) * DIM;
        #pragma unroll
        for (int i = 0; i < 4; i++) {
            int w = w0 + i;
            int x0 = rj[w] * DIM + cj[w];
            float4 v;
            v.x = (x0 +  0 < lim) ? X[base + x0 +  0] : 0.f;
            v.y = (x0 + 32 < lim) ? X[base + x0 + 32] : 0.f;
            v.z = (x0 + 64 < lim) ? X[base + x0 + 64] : 0.f;
            v.w = (x0 + 96 < lim) ? X[base + x0 + 96] : 0.f;
            vb[i] = v;
        }
    };
    auto cvt_wave = [&](float* abuf, int w0, const float4* vb) {
        #pragma unroll
        for (int i = 0; i < 4; i++) {
            int w = w0 + i;
            uint32_t* p = (uint32_t*)(abuf + woff[w]);
            p[0]  = f2tf32(vb[i].x);
            p[32] = f2tf32(vb[i].y);
            p[64] = f2tf32(vb[i].z);
            p[96] = f2tf32(vb[i].w);
        }
    };

    const int wm = (wid >> 2) * 32;
    const int wn = (wid & 3) * 32;
    const int g  = lid >> 2;
    const int kk = lid & 3;
    const int cr = lid >> 2;
    const int cc = (lid & 3) * 2;
    const float* sBias = smf + SM_BIAS / 4;
    float* W = smf + SM_W / 4;

    int curM = 0;
    loadW(0);
    if ((int)blockIdx.x < nTot) {
        float4 vb[4];
        int t0 = blockIdx.x % nT;
        ldg_wave(t0, 0, vb);
        cvt_wave(smf + SM_ABUF / 4, 0, vb);
        ldg_wave(t0, 4, vb);
        cvt_wave(smf + SM_ABUF / 4, 4, vb);
    }
    __syncthreads();

    const int aBase0 = (wm + g) * WROW + kk * 2;
    int bBase[4];
    #pragma unroll
    for (int nt = 0; nt < 4; nt++)
        bBase[nt] = (wn + nt * 8 + g) * WROW + kk * 2;

    int pb = 0;
    for (int idx = blockIdx.x; idx < nTot; idx += gridDim.x, pb ^= 1) {
        float* cur = smf + SM_ABUF / 4 + pb * (ABYTES / 4);
        float* nxt = smf + SM_ABUF / 4 + (pb ^ 1) * (ABYTES / 4);
        const int idxn = idx + gridDim.x;
        const bool hn = idxn < nTot;
        const int t = idx % nT;

        float acc[2][4][4];
        #pragma unroll
        for (int i = 0; i < 2; i++)
            #pragma unroll
            for (int j = 0; j < 4; j++)
                #pragma unroll
                for (int u = 0; u < 4; u++) acc[i][j][u] = 0.f;

        float4 vb[4];
        if (hn) ldg_wave(idxn % nT, 0, vb);

        #pragma unroll
        for (int half = 0; half < 2; half++) {
            #pragma unroll
            for (int ks = half * 8; ks < half * 8 + 8; ks++) {
                const int ko = ks * 8;
                uint2 aLo[2], aHi[2];
                #pragma unroll
                for (int mt = 0; mt < 2; mt++) {
                    aLo[mt] = *(const uint2*)(cur + aBase0 + mt * 16 * WROW + ko);
                    aHi[mt] = *(const uint2*)(cur + aBase0 + mt * 16 * WROW + 8 * WROW + ko);
                }
                uint2 bf[4];
                #pragma unroll
                for (int nt = 0; nt < 4; nt++)
                    bf[nt] = *(const uint2*)(W + bBase[nt] + ko);
                #pragma unroll
                for (int mt = 0; mt < 2; mt++) {
                    mma_tf32(acc[mt][0], aLo[mt].x, aHi[mt].x, aLo[mt].y, aHi[mt].y,
                             bf[0].x, bf[0].y);
                    mma_tf32(acc[mt][1], aLo[mt].x, aHi[mt].x, aLo[mt].y, aHi[mt].y,
                             bf[1].x, bf[1].y);
                    mma_tf32(acc[mt][2], aLo[mt].x, aHi[mt].x, aLo[mt].y, aHi[mt].y,
                             bf[2].x, bf[2].y);
                    mma_tf32(acc[mt][3], aLo[mt].x, aHi[mt].x, aLo[mt].y, aHi[mt].y,
                             bf[3].x, bf[3].y);
                }
            }
            if (hn) {
                cvt_wave(nxt, half * 4, vb);
                if (half == 0) ldg_wave(idxn % nT, 4, vb);
            }
        }

        // epilogue
        const int m = idx / nT;
        float* C = (m == 0) ? Cq : (m == 1) ? Ck : Cv;
        const int row0 = t * 128;
        #pragma unroll
        for (int mt = 0; mt < 2; mt++) {
            #pragma unroll
            for (int nt = 0; nt < 4; nt++) {
                int col = wn + nt * 8 + cc;
                float b0 = sBias[col], b1 = sBias[col + 1];
                int r1 = row0 + wm + mt * 16 + cr;
                if (r1 < M) {
                    float2 o; o.x = acc[mt][nt][0] + b0; o.y = acc[mt][nt][1] + b1;
                    *(float2*)(C + (size_t)r1 * DIM + col) = o;
                }
                int r2 = r1 + 8;
                if (r2 < M) {
                    float2 o; o.x = acc[mt][nt][2] + b0; o.y = acc[mt][nt][3] + b1;
                    *(float2*)(C + (size_t)r2 * DIM + col) = o;
                }
            }
        }
        __syncthreads();                  // all W/A reads done
        if (hn) {
            int mn = idxn / nT;
            if (mn != curM) {             // uniform condition across block
                curM = mn;
                loadW(mn);
                __syncthreads();          // W ready before next MMA
            }
        }
    }
}

// ------------------------ E GEMM (single matrix) ----------------------------
__global__ __launch_bounds__(GTHREADS, 1)
void gemm_tf32_kernel(const float* __restrict__ X,
                      const float* __restrict__ Wimg,
                      const float* __restrict__ bias,
                      float* __restrict__ C, int M, int nT) {
    extern __shared__ char smem[];
    float* smf = (float*)smem;
    const int tid = threadIdx.x;
    const int wid = tid >> 5;
    const int lid = tid & 31;

    {
        const int4* s = (const int4*)Wimg;
        int4* d = (int4*)(smem + SM_W);
        #pragma unroll
        for (int i = tid; i < ABYTES / 16; i += GTHREADS) d[i] = s[i];
    }
    if (tid < 128) smf[SM_BIAS / 4 + tid] = bias[tid];

    int rj[8], cj[8], woff[8];
    #pragma unroll
    for (int w = 0; w < 8; w++) {
        int j  = tid + w * GTHREADS;
        rj[w] = j >> 5;
        cj[w] = j & 31;
        woff[w] = rj[w] * WROW + ((cj[w] >> 3) << 3) + ((cj[w] & 3) << 1)
                + ((cj[w] >> 2) & 1);
    }

    auto ldg_wave = [&](int t, int w0, float4* vb) {
        const size_t base = (size_t)t * 128 * DIM;
        const int lim = (M - t * 128) * DIM;
        #pragma unroll
        for (int i = 0; i < 4; i++) {
            int w = w0 + i;
            int x0 = rj[w] * DIM + cj[w];
            float4 v;
            v.x = (x0 +  0 < lim) ? X[base + x0 +  0] : 0.f;
            v.y = (x0 + 32 < lim) ? X[base + x0 + 32] : 0.f;
            v.z = (x0 + 64 < lim) ? X[base + x0 + 64] : 0.f;
            v.w = (x0 + 96 < lim) ? X[base + x0 + 96] : 0.f;
            vb[i] = v;
        }
    };
    auto cvt_wave = [&](float* abuf, int w0, const float4* vb) {
        #pragma unroll
        for (int i = 0; i < 4; i++) {
            int w = w0 + i;
            uint32_t* p = (uint32_t*)(abuf + woff[w]);
            p[0]  = f2tf32(vb[i].x);
            p[32] = f2tf32(vb[i].y);
            p[64] = f2tf32(vb[i].z);
            p[96] = f2tf32(vb[i].w);
        }
    };

    const int wm = (wid >> 2) * 32;
    const int wn = (wid & 3) * 32;
    const int g  = lid >> 2;
    const int kk = lid & 3;
    const int cr = lid >> 2;
    const int cc = (lid & 3) * 2;
    const float* sBias = smf + SM_BIAS / 4;
    float* W = smf + SM_W / 4;

    if ((int)blockIdx.x < nT) {
        float4 vb[4];
        ldg_wave(blockIdx.x, 0, vb);
        cvt_wave(smf + SM_ABUF / 4, 0, vb);
        ldg_wave(blockIdx.x, 4, vb);
        cvt_wave(smf + SM_ABUF / 4, 4, vb);
    }
    __syncthreads();

    const int aBase0 = (wm + g) * WROW + kk * 2;
    int bBase[4];
    #pragma unroll
    for (int nt = 0; nt < 4; nt++)
        bBase[nt] = (wn + nt * 8 + g) * WROW + kk * 2;

    int pb = 0;
    for (int t = blockIdx.x; t < nT; t += gridDim.x, pb ^= 1) {
        float* cur = smf + SM_ABUF / 4 + pb * (ABYTES / 4);
        float* nxt = smf + SM_ABUF / 4 + (pb ^ 1) * (ABYTES / 4);
        const int tn = t + gridDim.x;
        const bool hn = tn < nT;

        float acc[2][4][4];
        #pragma unroll
        for (int i = 0; i < 2; i++)
            #pragma unroll
            for (int j = 0; j < 4; j++)
                #pragma unroll
                for (int u = 0; u < 4; u++) acc[i][j][u] = 0.f;

        float4 vb[4];
        if (hn) ldg_wave(tn, 0, vb);

        #pragma unroll
        for (int half = 0; half < 2; half++) {
            #pragma unroll
            for (int ks = half * 8; ks < half * 8 + 8; ks++) {
                const int ko = ks * 8;
                uint2 aLo[2], aHi[2];
                #pragma unroll
                for (int mt = 0; mt < 2; mt++) {
                    aLo[mt] = *(const uint2*)(cur + aBase0 + mt * 16 * WROW + ko);
                    aHi[mt] = *(const uint2*)(cur + aBase0 + mt * 16 * WROW + 8 * WROW + ko);
                }
                uint2 bf[4];
                #pragma unroll
                for (int nt = 0; nt < 4; nt++)
                    bf[nt] = *(const uint2*)(W + bBase[nt] + ko);
                #pragma unroll
                for (int mt = 0; mt < 2; mt++) {
                    mma_tf32(acc[mt][0], aLo[mt].x, aHi[mt].x, aLo[mt].y, aHi[mt].y,
                             bf[0].x, bf[0].y);
                    mma_tf32(acc[mt][1], aLo[mt].x, aHi[mt].x, aLo[mt].y, aHi[mt].y,
                             bf[1].x, bf[1].y);
                    mma_tf32(acc[mt][2], aLo[mt].x, aHi[mt].x, aLo[mt].y, aHi[mt].y,
                             bf[2].x, bf[2].y);
                    mma_tf32(acc[mt][3], aLo[mt].x, aHi[mt].x, aLo[mt].y, aHi[mt].y,
                             bf[3].x, bf[3].y);
                }
            }
            if (hn) {
                cvt_wave(nxt, half * 4, vb);
                if (half == 0) ldg_wave(tn, 4, vb);
            }
        }

        const int row0 = t * 128;
        #pragma unroll
        for (int mt = 0; mt < 2; mt++) {
            #pragma unroll
            for (int nt = 0; nt < 4; nt++) {
                int col = wn + nt * 8 + cc;
                float b0 = sBias[col], b1 = sBias[col + 1];
                int r1 = row0 + wm + mt * 16 + cr;
                if (r1 < M) {
                    float2 o; o.x = acc[mt][nt][0] + b0; o.y = acc[mt][nt][1] + b1;
                    *(float2*)(C + (size_t)r1 * DIM + col) = o;
                }
                int r2 = r1 + 8;
                if (r2 < M) {
                    float2 o; o.x = acc[mt][nt][2] + b0; o.y = acc[mt][nt][3] + b1;
                    *(float2*)(C + (size_t)r2 * DIM + col) = o;
                }
            }
        }
        __syncthreads();
    }
}

// --------------------------- edge scatter kernel (2-edge ILP) ---------------
__global__ __launch_bounds__(256)
void edge_kernel(const int* __restrict__ ei, const float* __restrict__ E,
                 float* __restrict__ wV, int nE) {
    const int lid   = threadIdx.x & 31;
    const int warp  = (blockIdx.x * blockDim.x + threadIdx.x) >> 5;
    const int nwarp = (gridDim.x * blockDim.x) >> 5;
    const int h  = lid >> 2;
    const int i4 = lid & 3;

    for (int e = warp * 2; e < nE; e += nwarp * 2) {
        const int eB = e + 1;
        const bool hB = eB < nE;

        int srcA = __ldg(ei + e);
        int dstA = __ldg(ei + nE + e);
        int srcB = hB ? __ldg(ei + eB)      : srcA;
        int dstB = hB ? __ldg(ei + nE + eB) : dstA;

        float4 kA  = *(const float4*)(g_K + (size_t)srcA * DIM + 4 * lid);
        float4 qA  = *(const float4*)(g_Q + (size_t)dstA * DIM + 4 * lid);
        float4 eA  = __ldg((const float4*)(E + (size_t)e  * DIM + 4 * lid));
        float4 vA  = *(const float4*)(g_V + (size_t)srcA * DIM + 4 * lid);
        float4 kB  = *(const float4*)(g_K + (size_t)srcB * DIM + 4 * lid);
        float4 qB  = *(const float4*)(g_Q + (size_t)dstB * DIM + 4 * lid);
        float4 eB4 = hB ? __ldg((const float4*)(E + (size_t)eB * DIM + 4 * lid))
                        : make_float4(0.f, 0.f, 0.f, 0.f);
        float4 vB  = *(const float4*)(g_V + (size_t)srcB * DIM + 4 * lid);

        float tA = kA.x * qA.x * eA.x + kA.y * qA.y * eA.y
                 + kA.z * qA.z * eA.z + kA.w * qA.w * eA.w;
        float tB = kB.x * qB.x * eB4.x + kB.y * qB.y * eB4.y
                 + kB.z * qB.z * eB4.z + kB.w * qB.w * eB4.w;
        tA += __shfl_xor_sync(0xFFFFFFFFu, tA, 1);
        tB += __shfl_xor_sync(0xFFFFFFFFu, tB, 1);
        tA += __shfl_xor_sync(0xFFFFFFFFu, tA, 2);
        tB += __shfl_xor_sync(0xFFFFFFFFu, tB, 2);
        tA = fminf(fmaxf(tA * 0.25f, -5.f), 5.f);
        tB = fminf(fmaxf(tB * 0.25f, -5.f), 5.f);
        float sA = __expf(tA);
        float sB = __expf(tB);

        red4(wV + (size_t)dstA * DIM + 4 * lid,
             vA.x * sA, vA.y * sA, vA.z * sA, vA.w * sA);
        if (i4 == 0) atomicAdd(&g_Z[dstA * NH + h], sA);
        if (hB) {
            red4(wV + (size_t)dstB * DIM + 4 * lid,
                 vB.x * sB, vB.y * sB, vB.z * sB, vB.w * sB);
            if (i4 == 0) atomicAdd(&g_Z[dstB * NH + h], sB);
        }
    }
}

// ----------------------------- normalize (float4) ---------------------------
__global__ __launch_bounds__(256)
void normalize_kernel(float* __restrict__ out, int n4) {
    int i = blockIdx.x * blockDim.x + threadIdx.x;
    if (i >= n4) return;
    int node = i >> 5;
    int h    = (i >> 2) & 7;
    float z  = g_Z[node * NH + h];
    float inv = 1.0f / (z + 1e-6f);
    float4 o = ((const float4*)out)[i];
    o.x *= inv; o.y *= inv; o.z *= inv; o.w *= inv;
    ((float4*)out)[i] = o;
}

// ----------------------------- launcher -------------------------------------
extern "C" void kernel_launch(void* const* d_in, const int* in_sizes, int n_in,
                              void* d_out, int out_size) {
    const float* x   = (const float*)d_in[0];
    const float* ea  = (const float*)d_in[1];
    const int*   ei  = (const int*)d_in[2];
    const float* Wq  = (const float*)d_in[3];
    const float* bq  = (const float*)d_in[4];
    const float* Wk  = (const float*)d_in[5];
    const float* bk  = (const float*)d_in[6];
    const float* We  = (const float*)d_in[7];
    const float* be  = (const float*)d_in[8];
    const float* Wv  = (const float*)d_in[9];
    const float* bv  = (const float*)d_in[10];
    float* out = (float*)d_out;

    const int nN = in_sizes[0] / DIM;     // 50000
    const int nE = in_sizes[1] / DIM;     // 800000

    float *pQ, *pK, *pV, *pE, *pZ, *pW;
    cudaGetSymbolAddress((void**)&pQ, g_Q);
    cudaGetSymbolAddress((void**)&pK, g_K);
    cudaGetSymbolAddress((void**)&pV, g_V);
    cudaGetSymbolAddress((void**)&pE, g_E);
    cudaGetSymbolAddress((void**)&pZ, g_Z);
    cudaGetSymbolAddress((void**)&pW, g_Wimg);

    cudaMemsetAsync(d_out, 0, (size_t)out_size * sizeof(float));
    cudaMemsetAsync(pZ, 0, (size_t)nN * NH * sizeof(float));

    prep_w_kernel<<<(4 * DIM * DIM + 255) / 256, 256>>>(Wq, Wk, Wv, We);

    cudaFuncSetAttribute(qkv_fused_kernel, cudaFuncAttributeMaxDynamicSharedMemorySize, SM_TOTAL);
    cudaFuncSetAttribute(gemm_tf32_kernel, cudaFuncAttributeMaxDynamicSharedMemorySize, SM_TOTAL);

    const int tN = (nN + 127) / 128;    // 391
    const int tE = (nE + 127) / 128;    // 6250
    qkv_fused_kernel<<<148, GTHREADS, SM_TOTAL>>>(x, bq, bk, bv, pQ, pK, pV, nN, tN);
    gemm_tf32_kernel<<<148, GTHREADS, SM_TOTAL>>>(ea, pW + 3 * DIM * WROW, be, pE, nE, tE);

    edge_kernel<<<4096, 256>>>(ei, pE, out, nE);

    int n4 = nN * DIM / 4;
    normalize_kernel<<<(n4 + 255) / 256, 256>>>(out, n4);
}